// round 3
// baseline (speedup 1.0000x reference)
#include <cuda_runtime.h>
#include <cuda_bf16.h>
#include <cstdint>

// Problem constants
#define B_  2
#define L_  4096
#define HS_ 2048
#define NH_ 16
#define HD_ 128
#define FD_ 256
#define NROWS (B_*L_)            // 8192
#define NTOK  (B_*L_*NH_)        // 131072 token-head rows

// Scratch layout (floats)
#define OFF_Q    ((size_t)0)
#define OFF_K    ((size_t)16777216)
#define OFF_V    ((size_t)33554432)
#define OFF_TMP  ((size_t)50331648)
#define OFF_QF   ((size_t)83886080)
#define OFF_KF   ((size_t)117440512)
#define OFF_KV   ((size_t)150994944)
#define OFF_KSUM ((size_t)152043520)
#define OFF_ATTN ((size_t)152051712)
#define SCRATCH_TOTAL ((size_t)168828928)

__device__ float g_scratch[SCRATCH_TOTAL];

// ---------------------------------------------------------------------------
// Generic SGEMM: C[M,N] = A[M,K] @ B[K,N] + bias[N], optional relu.
// BM=BN=128, BK=8, TM=TN=8, 256 threads.
// ---------------------------------------------------------------------------
#define BM 128
#define BN 128
#define BK 8
#define TM 8
#define TN 8

__global__ __launch_bounds__(256) void sgemm_kernel(
    const float* __restrict__ A, const float* __restrict__ Bm,
    const float* __restrict__ bias, float* __restrict__ C,
    int M, int N, int K, int relu)
{
    __shared__ float As[BK][BM];
    __shared__ float Bs[BK][BN];

    const int tid = threadIdx.x;
    const int bx = blockIdx.x;   // N tile
    const int by = blockIdx.y;   // M tile

    const float* Ab = A + (size_t)by * BM * K;
    const float* Bb = Bm + (size_t)bx * BN;
    float* Cb = C + (size_t)by * BM * N + (size_t)bx * BN;

    const int aRow = tid >> 1;          // 0..127
    const int aCol = (tid & 1) * 4;     // 0 or 4
    const int bRow = tid >> 5;          // 0..7
    const int bCol = (tid & 31) * 4;    // 0..124

    const int tRow = (tid >> 4) * TM;   // 0..120
    const int tCol = (tid & 15) * TN;   // 0..120

    float acc[TM][TN];
    #pragma unroll
    for (int i = 0; i < TM; i++)
        #pragma unroll
        for (int j = 0; j < TN; j++) acc[i][j] = 0.f;

    for (int k0 = 0; k0 < K; k0 += BK) {
        float4 av = *(const float4*)(Ab + (size_t)aRow * K + k0 + aCol);
        As[aCol + 0][aRow] = av.x;
        As[aCol + 1][aRow] = av.y;
        As[aCol + 2][aRow] = av.z;
        As[aCol + 3][aRow] = av.w;
        float4 bv = *(const float4*)(Bb + (size_t)(k0 + bRow) * N + bCol);
        *(float4*)&Bs[bRow][bCol] = bv;
        __syncthreads();

        #pragma unroll
        for (int kk = 0; kk < BK; kk++) {
            float ar[TM], br[TN];
            #pragma unroll
            for (int i = 0; i < TM; i++) ar[i] = As[kk][tRow + i];
            #pragma unroll
            for (int j = 0; j < TN; j++) br[j] = Bs[kk][tCol + j];
            #pragma unroll
            for (int i = 0; i < TM; i++)
                #pragma unroll
                for (int j = 0; j < TN; j++) acc[i][j] += ar[i] * br[j];
        }
        __syncthreads();
    }

    #pragma unroll
    for (int i = 0; i < TM; i++) {
        #pragma unroll
        for (int j = 0; j < TN; j += 4) {
            float4 v;
            float b0 = bias[bx * BN + tCol + j + 0];
            float b1 = bias[bx * BN + tCol + j + 1];
            float b2 = bias[bx * BN + tCol + j + 2];
            float b3 = bias[bx * BN + tCol + j + 3];
            v.x = acc[i][j + 0] + b0;
            v.y = acc[i][j + 1] + b1;
            v.z = acc[i][j + 2] + b2;
            v.w = acc[i][j + 3] + b3;
            if (relu) {
                v.x = fmaxf(v.x, 0.f); v.y = fmaxf(v.y, 0.f);
                v.z = fmaxf(v.z, 0.f); v.w = fmaxf(v.w, 0.f);
            }
            *(float4*)(Cb + (size_t)(tRow + i) * N + tCol + j) = v;
        }
    }
}

// ---------------------------------------------------------------------------
// LayerNorm over FD=256 per row, optionally multiplied by (1+mask[b,l]).
// One block (256 threads) per row; row index = (b*L+l)*NH + h.
// ---------------------------------------------------------------------------
__global__ __launch_bounds__(256) void ln_mask_kernel(
    float* __restrict__ x, const float* __restrict__ gamma,
    const float* __restrict__ beta, const float* __restrict__ mask,
    int use_mask)
{
    const int row = blockIdx.x;
    const int f = threadIdx.x;
    const size_t base = (size_t)row * FD_;
    float v = x[base + f];

    float s = v, s2 = v * v;
    #pragma unroll
    for (int o = 16; o; o >>= 1) {
        s  += __shfl_down_sync(0xffffffffu, s,  o);
        s2 += __shfl_down_sync(0xffffffffu, s2, o);
    }
    __shared__ float rs[8], rs2[8];
    __shared__ float smu, srstd;
    const int wid = f >> 5, lane = f & 31;
    if (lane == 0) { rs[wid] = s; rs2[wid] = s2; }
    __syncthreads();
    if (f == 0) {
        float ts = 0.f, ts2 = 0.f;
        #pragma unroll
        for (int i = 0; i < 8; i++) { ts += rs[i]; ts2 += rs2[i]; }
        float mu = ts * (1.f / FD_);
        float var = ts2 * (1.f / FD_) - mu * mu;
        smu = mu;
        srstd = rsqrtf(var + 1e-5f);
    }
    __syncthreads();
    float y = (v - smu) * srstd * gamma[f] + beta[f];
    if (use_mask) y *= (1.f + mask[row >> 4]);   // row/NH -> b*L+l
    x[base + f] = y;
}

// ---------------------------------------------------------------------------
// k_sum: zero + partial atomic reduce over L
// ---------------------------------------------------------------------------
__global__ void zero_ksum_kernel(float* __restrict__ ks)
{
    ks[blockIdx.x * FD_ + threadIdx.x] = 0.f;
}

__global__ __launch_bounds__(256) void ksum_kernel(
    const float* __restrict__ kf, float* __restrict__ ks)
{
    const int bh = blockIdx.x;            // 0..31
    const int chunk = blockIdx.y;         // 0..15 (256 l each)
    const int b = bh >> 4, h = bh & 15;
    const int f = threadIdx.x;
    float acc = 0.f;
    const int l0 = chunk * 256;
    for (int l = l0; l < l0 + 256; ++l)
        acc += kf[((size_t)((b * L_ + l) * NH_ + h)) * FD_ + f];
    atomicAdd(&ks[bh * FD_ + f], acc);
}

// ---------------------------------------------------------------------------
// kv[bh][f][d] = sum_l k_feat[b,h,l,f] * v[b,h,l,d]
// BMf=32 (f tile), BNd=128 (full d), BKl=16, 256 threads, 2x8 per thread.
// ---------------------------------------------------------------------------
#define KV_BM 32
#define KV_BK 16

__global__ __launch_bounds__(256) void kv_kernel(
    const float* __restrict__ kf, const float* __restrict__ v,
    float* __restrict__ kv)
{
    const int bh = blockIdx.x;
    const int f0 = blockIdx.y * KV_BM;
    const int b = bh >> 4, h = bh & 15;
    const int tid = threadIdx.x;

    __shared__ float Ks[KV_BK][KV_BM];
    __shared__ float Vs[KV_BK][HD_];

    float acc[2][8];
    #pragma unroll
    for (int i = 0; i < 2; i++)
        #pragma unroll
        for (int j = 0; j < 8; j++) acc[i][j] = 0.f;

    const int tRow = (tid >> 4) * 2;   // f within tile: 0..30
    const int tCol = (tid & 15) * 8;   // d: 0..120

    const int klr = tid >> 3;          // 0..31 (only <16 used with guard)
    const int kfc = (tid & 7) * 4;     // 0..28

    for (int l0 = 0; l0 < L_; l0 += KV_BK) {
        if (tid < 128) {
            float4 a = *(const float4*)(kf +
                ((size_t)((b * L_ + l0 + klr) * NH_ + h)) * FD_ + f0 + kfc);
            Ks[klr][kfc + 0] = a.x; Ks[klr][kfc + 1] = a.y;
            Ks[klr][kfc + 2] = a.z; Ks[klr][kfc + 3] = a.w;
        }
        #pragma unroll
        for (int r = 0; r < 2; r++) {
            int idx = tid + 256 * r;
            int lr = idx >> 5, dc = (idx & 31) * 4;
            *(float4*)&Vs[lr][dc] = *(const float4*)(v +
                ((size_t)((b * L_ + l0 + lr) * NH_ + h)) * HD_ + dc);
        }
        __syncthreads();
        #pragma unroll
        for (int ll = 0; ll < KV_BK; ll++) {
            float ar[2], br[8];
            ar[0] = Ks[ll][tRow + 0];
            ar[1] = Ks[ll][tRow + 1];
            #pragma unroll
            for (int j = 0; j < 8; j++) br[j] = Vs[ll][tCol + j];
            #pragma unroll
            for (int i = 0; i < 2; i++)
                #pragma unroll
                for (int j = 0; j < 8; j++) acc[i][j] += ar[i] * br[j];
        }
        __syncthreads();
    }

    #pragma unroll
    for (int i = 0; i < 2; i++)
        #pragma unroll
        for (int j = 0; j < 8; j += 4) {
            float4 o;
            o.x = acc[i][j + 0]; o.y = acc[i][j + 1];
            o.z = acc[i][j + 2]; o.w = acc[i][j + 3];
            *(float4*)(kv + ((size_t)bh * FD_ + f0 + tRow + i) * HD_ + tCol + j) = o;
        }
}

// ---------------------------------------------------------------------------
// attn[b,l,h*128+d] = (sum_f qf[b,h,l,f]*kv[bh,f,d]) / (sum_f qf*ksum + 1e-8)
// BMl=64, full d=128, BKf=16, 256 threads, 4x8 per thread.
// ---------------------------------------------------------------------------
#define AT_BM 64
#define AT_BK 16

__global__ __launch_bounds__(256) void attn_kernel(
    const float* __restrict__ qf, const float* __restrict__ kv,
    const float* __restrict__ ksum, float* __restrict__ out)
{
    const int bh = blockIdx.x;
    const int b = bh >> 4, h = bh & 15;
    const int l0 = blockIdx.y * AT_BM;
    const int tid = threadIdx.x;

    __shared__ float Qs[AT_BK][AT_BM];   // [f][l]
    __shared__ float KVs[AT_BK][HD_];
    __shared__ float KSs[AT_BK];
    __shared__ float sden[AT_BM];

    float acc[4][8];
    #pragma unroll
    for (int i = 0; i < 4; i++)
        #pragma unroll
        for (int j = 0; j < 8; j++) acc[i][j] = 0.f;
    float dacc[4] = {0.f, 0.f, 0.f, 0.f};

    const int tRow = (tid >> 4) * 4;   // l: 0..60
    const int tCol = (tid & 15) * 8;   // d: 0..120
    const int qlr = tid >> 2;          // 0..63 (l)
    const int qfc = (tid & 3) * 4;     // 0..12 (f)

    for (int f0 = 0; f0 < FD_; f0 += AT_BK) {
        float4 qv = *(const float4*)(qf +
            ((size_t)((b * L_ + l0 + qlr) * NH_ + h)) * FD_ + f0 + qfc);
        Qs[qfc + 0][qlr] = qv.x; Qs[qfc + 1][qlr] = qv.y;
        Qs[qfc + 2][qlr] = qv.z; Qs[qfc + 3][qlr] = qv.w;
        #pragma unroll
        for (int r = 0; r < 2; r++) {
            int idx = tid + 256 * r;
            int fr = idx >> 5, dc = (idx & 31) * 4;
            *(float4*)&KVs[fr][dc] = *(const float4*)(kv +
                ((size_t)bh * FD_ + f0 + fr) * HD_ + dc);
        }
        if (tid < AT_BK) KSs[tid] = ksum[bh * FD_ + f0 + tid];
        __syncthreads();
        #pragma unroll
        for (int ll = 0; ll < AT_BK; ll++) {
            float ar[4], br[8];
            #pragma unroll
            for (int i = 0; i < 4; i++) ar[i] = Qs[ll][tRow + i];
            #pragma unroll
            for (int j = 0; j < 8; j++) br[j] = KVs[ll][tCol + j];
            #pragma unroll
            for (int i = 0; i < 4; i++)
                #pragma unroll
                for (int j = 0; j < 8; j++) acc[i][j] += ar[i] * br[j];
            if ((tid & 15) == 0) {
                float ksv = KSs[ll];
                #pragma unroll
                for (int i = 0; i < 4; i++) dacc[i] += ar[i] * ksv;
            }
        }
        __syncthreads();
    }

    if ((tid & 15) == 0) {
        #pragma unroll
        for (int i = 0; i < 4; i++) sden[tRow + i] = dacc[i];
    }
    __syncthreads();

    #pragma unroll
    for (int i = 0; i < 4; i++) {
        float inv = 1.f / (sden[tRow + i] + 1e-8f);
        #pragma unroll
        for (int j = 0; j < 8; j += 4) {
            float4 o;
            o.x = acc[i][j + 0] * inv; o.y = acc[i][j + 1] * inv;
            o.z = acc[i][j + 2] * inv; o.w = acc[i][j + 3] * inv;
            *(float4*)(out + ((size_t)(b * L_ + l0 + tRow + i)) * HS_ +
                       h * HD_ + tCol + j) = o;
        }
    }
}

// ---------------------------------------------------------------------------
// Host launch
// ---------------------------------------------------------------------------
extern "C" void kernel_launch(void* const* d_in, const int* in_sizes, int n_in,
                              void* d_out, int out_size)
{
    (void)in_sizes; (void)n_in; (void)out_size;
    const float* X    = (const float*)d_in[0];
    const float* mask = (const float*)d_in[1];
    const float* Wq   = (const float*)d_in[2];
    const float* bq   = (const float*)d_in[3];
    const float* Wk   = (const float*)d_in[4];
    const float* bk   = (const float*)d_in[5];
    const float* Wv   = (const float*)d_in[6];
    const float* bv   = (const float*)d_in[7];
    const float* Wo   = (const float*)d_in[8];
    const float* bo   = (const float*)d_in[9];
    const float* Wf1  = (const float*)d_in[10];
    const float* bf1  = (const float*)d_in[11];
    const float* Wf2  = (const float*)d_in[12];
    const float* bf2  = (const float*)d_in[13];
    const float* ln_g = (const float*)d_in[14];
    const float* ln_b = (const float*)d_in[15];

    float* scratch = nullptr;
    cudaGetSymbolAddress((void**)&scratch, g_scratch);
    float* q     = scratch + OFF_Q;
    float* k     = scratch + OFF_K;
    float* v     = scratch + OFF_V;
    float* tmp   = scratch + OFF_TMP;
    float* qfeat = scratch + OFF_QF;
    float* kfeat = scratch + OFF_KF;
    float* kvbuf = scratch + OFF_KV;
    float* ksbuf = scratch + OFF_KSUM;
    float* attn  = scratch + OFF_ATTN;

    dim3 blk(256);
    dim3 gBig(HS_ / BN, NROWS / BM);     // (16, 64)
    dim3 gF1(FD_ / BN, NTOK / BM);       // (2, 1024)

    // QKV projections -> [B, L, NH, HD]
    sgemm_kernel<<<gBig, blk>>>(X, Wq, bq, q, NROWS, HS_, HS_, 0);
    sgemm_kernel<<<gBig, blk>>>(X, Wk, bk, k, NROWS, HS_, HS_, 0);
    sgemm_kernel<<<gBig, blk>>>(X, Wv, bv, v, NROWS, HS_, HS_, 0);

    // feature_map(q)
    sgemm_kernel<<<gF1, blk>>>(q, Wf1, bf1, tmp, NTOK, FD_, HD_, 1);
    sgemm_kernel<<<gF1, blk>>>(tmp, Wf2, bf2, qfeat, NTOK, FD_, FD_, 0);
    ln_mask_kernel<<<NTOK, 256>>>(qfeat, ln_g, ln_b, mask, 0);

    // feature_map(k) * (1 + mask)
    sgemm_kernel<<<gF1, blk>>>(k, Wf1, bf1, tmp, NTOK, FD_, HD_, 1);
    sgemm_kernel<<<gF1, blk>>>(tmp, Wf2, bf2, kfeat, NTOK, FD_, FD_, 0);
    ln_mask_kernel<<<NTOK, 256>>>(kfeat, ln_g, ln_b, mask, 1);

    // k_sum
    zero_ksum_kernel<<<B_ * NH_, 256>>>(ksbuf);
    ksum_kernel<<<dim3(B_ * NH_, 16), 256>>>(kfeat, ksbuf);

    // kv
    kv_kernel<<<dim3(B_ * NH_, FD_ / KV_BM), 256>>>(kfeat, v, kvbuf);

    // attn (with denom) -> [B, L, HS]
    attn_kernel<<<dim3(B_ * NH_, L_ / AT_BM), 256>>>(qfeat, kvbuf, ksbuf, attn);

    // output projection
    sgemm_kernel<<<gBig, blk>>>(attn, Wo, bo, (float*)d_out, NROWS, HS_, HS_, 0);
}

// round 7
// speedup vs baseline: 2.6852x; 2.6852x over previous
#include <cuda_runtime.h>
#include <cuda_bf16.h>
#include <cstdint>

// Problem constants
#define B_  2
#define L_  4096
#define HS_ 2048
#define NH_ 16
#define HD_ 128
#define FD_ 256
#define NROWS (B_*L_)            // 8192
#define NTOK  (B_*L_*NH_)        // 131072

// Scratch layout (floats)
#define OFF_Q    ((size_t)0)
#define OFF_K    ((size_t)16777216)
#define OFF_V    ((size_t)33554432)
#define OFF_TMP  ((size_t)50331648)
#define OFF_QF   ((size_t)83886080)
#define OFF_KF   ((size_t)117440512)
#define OFF_KV   ((size_t)150994944)
#define OFF_KSUM ((size_t)152043520)
#define OFF_ATTN ((size_t)152051712)
#define OFF_WQT  ((size_t)168828928)
#define OFF_WKT  (OFF_WQT + 4194304)
#define OFF_WVT  (OFF_WKT + 4194304)
#define OFF_WOT  (OFF_WVT + 4194304)
#define OFF_WF1T (OFF_WOT + 4194304)
#define OFF_WF2T (OFF_WF1T + 32768)
#define OFF_XR   (OFF_WF2T + 65536)
#define SCRATCH_TOTAL (OFF_XR + 16777216)

__device__ float g_scratch[SCRATCH_TOTAL];

// ---------------------------------------------------------------------------
// Helpers
// ---------------------------------------------------------------------------
__device__ __forceinline__ uint32_t smem_u32(const void* p) {
    uint32_t a;
    asm("{ .reg .u64 t; cvta.to.shared.u64 t, %1; cvt.u32.u64 %0, t; }"
        : "=r"(a) : "l"(p));
    return a;
}

__device__ __forceinline__ float rndtf32(float x) {
    uint32_t u;
    asm("cvt.rna.tf32.f32 %0, %1;" : "=r"(u) : "f"(x));
    return __uint_as_float(u);
}

#define CP_ASYNC16(saddr, gaddr) \
    asm volatile("cp.async.cg.shared.global [%0], [%1], 16;" \
                 :: "r"(saddr), "l"(gaddr))
#define CP_COMMIT() asm volatile("cp.async.commit_group;")

__device__ __forceinline__ void mma_tf32(float* d, const uint32_t* a,
                                         uint32_t b0, uint32_t b1) {
    asm volatile(
        "mma.sync.aligned.m16n8k8.row.col.f32.tf32.tf32.f32 "
        "{%0,%1,%2,%3}, {%4,%5,%6,%7}, {%8,%9}, {%0,%1,%2,%3};"
        : "+f"(d[0]), "+f"(d[1]), "+f"(d[2]), "+f"(d[3])
        : "r"(a[0]), "r"(a[1]), "r"(a[2]), "r"(a[3]), "r"(b0), "r"(b1));
}

// ---------------------------------------------------------------------------
// tf32 tensor-core GEMM via mma.sync (sm_80+ path, runs on tensor pipe):
// C[M,N] = A[M,K] @ BT[N,K]^T + bias[N], optional relu, optional tf32-round.
// CTA 128x128, BK=32, 8 warps (warp tile 32x64), cp.async 2-stage pipeline.
// SMEM rows padded to 36 floats -> conflict-free fragment LDS.
// ---------------------------------------------------------------------------
#define TSTRIDE 36
#define STAGE_FLOATS (2 * 128 * TSTRIDE)        // A + B, 9216 floats
#define STAGE_BYTES  (STAGE_FLOATS * 4)          // 36864
#define GEMM_SMEM    (2 * STAGE_BYTES)           // 73728

__global__ __launch_bounds__(256, 2) void gemm_tc_kernel(
    const float* __restrict__ A, const float* __restrict__ BT,
    const float* __restrict__ bias, float* __restrict__ C,
    int M, int N, int K, int relu, int rnd)
{
    extern __shared__ float sm[];
    const int tid = threadIdx.x;
    const int wid = tid >> 5, lane = tid & 31;
    const int wm = wid & 3, wn = wid >> 2;      // warp grid 4 (M) x 2 (N)
    const int gid = lane >> 2, tig = lane & 3;  // groupID, thread-in-group
    const int n0 = blockIdx.x * 128, m0 = blockIdx.y * 128;
    const uint32_t sbase = smem_u32(sm);

    float acc[2][8][4];
    #pragma unroll
    for (int mi = 0; mi < 2; mi++)
        #pragma unroll
        for (int ni = 0; ni < 8; ni++)
            #pragma unroll
            for (int j = 0; j < 4; j++) acc[mi][ni][j] = 0.f;

    const int nchunk = K >> 5;

    auto issue_chunk = [&](int c, int slot) {
        const float* Ag = A + (size_t)m0 * K + c * 32;
        const float* Bg = BT + (size_t)n0 * K + c * 32;
        const uint32_t sA = sbase + (uint32_t)slot * STAGE_BYTES;
        const uint32_t sB = sA + 128 * TSTRIDE * 4;
        #pragma unroll
        for (int r = 0; r < 4; r++) {
            const int idx = tid + 256 * r;
            const int row = idx >> 3, seg = idx & 7;
            const uint32_t so = (uint32_t)(row * TSTRIDE + seg * 4) * 4;
            CP_ASYNC16(sA + so, Ag + (size_t)row * K + seg * 4);
            CP_ASYNC16(sB + so, Bg + (size_t)row * K + seg * 4);
        }
    };

    issue_chunk(0, 0);
    CP_COMMIT();

    for (int c = 0; c < nchunk; c++) {
        if (c + 1 < nchunk) {
            issue_chunk(c + 1, (c + 1) & 1);
            CP_COMMIT();
            asm volatile("cp.async.wait_group 1;");
        } else {
            asm volatile("cp.async.wait_group 0;");
        }
        __syncthreads();

        const float* sA = sm + (size_t)(c & 1) * STAGE_FLOATS;
        const float* sB = sA + 128 * TSTRIDE;

        #pragma unroll
        for (int kk = 0; kk < 32; kk += 8) {
            uint32_t a[2][4];
            #pragma unroll
            for (int mi = 0; mi < 2; mi++) {
                const int r0 = wm * 32 + mi * 16 + gid;
                a[mi][0] = __float_as_uint(sA[r0 * TSTRIDE + kk + tig]);
                a[mi][1] = __float_as_uint(sA[(r0 + 8) * TSTRIDE + kk + tig]);
                a[mi][2] = __float_as_uint(sA[r0 * TSTRIDE + kk + tig + 4]);
                a[mi][3] = __float_as_uint(sA[(r0 + 8) * TSTRIDE + kk + tig + 4]);
            }
            #pragma unroll
            for (int ni = 0; ni < 8; ni++) {
                const int nb = wn * 64 + ni * 8 + gid;
                const uint32_t b0 = __float_as_uint(sB[nb * TSTRIDE + kk + tig]);
                const uint32_t b1 = __float_as_uint(sB[nb * TSTRIDE + kk + tig + 4]);
                mma_tf32(acc[0][ni], a[0], b0, b1);
                mma_tf32(acc[1][ni], a[1], b0, b1);
            }
        }
        __syncthreads();
    }

    // Epilogue
    #pragma unroll
    for (int mi = 0; mi < 2; mi++) {
        const int row = m0 + wm * 32 + mi * 16 + gid;
        #pragma unroll
        for (int ni = 0; ni < 8; ni++) {
            const int col = n0 + wn * 64 + ni * 8 + tig * 2;
            const float b0v = bias[col], b1v = bias[col + 1];
            float v0 = acc[mi][ni][0] + b0v;
            float v1 = acc[mi][ni][1] + b1v;
            float v2 = acc[mi][ni][2] + b0v;
            float v3 = acc[mi][ni][3] + b1v;
            if (relu) {
                v0 = fmaxf(v0, 0.f); v1 = fmaxf(v1, 0.f);
                v2 = fmaxf(v2, 0.f); v3 = fmaxf(v3, 0.f);
            }
            if (rnd) {
                v0 = rndtf32(v0); v1 = rndtf32(v1);
                v2 = rndtf32(v2); v3 = rndtf32(v3);
            }
            float2 o01; o01.x = v0; o01.y = v1;
            float2 o23; o23.x = v2; o23.y = v3;
            *(float2*)(C + (size_t)row * N + col) = o01;
            *(float2*)(C + (size_t)(row + 8) * N + col) = o23;
        }
    }
}

// ---------------------------------------------------------------------------
// Transpose + tf32-round: dst[C,R] = rnd(src[R,C]^T)
// ---------------------------------------------------------------------------
__global__ __launch_bounds__(256) void transpose_kernel(
    const float* __restrict__ src, float* __restrict__ dst, int R, int C)
{
    __shared__ float t[32][33];
    const int bx = blockIdx.x * 32;
    const int by = blockIdx.y * 32;
    const int tx = threadIdx.x, ty = threadIdx.y;
    #pragma unroll
    for (int i = 0; i < 32; i += 8)
        t[ty + i][tx] = src[(size_t)(by + ty + i) * C + bx + tx];
    __syncthreads();
    #pragma unroll
    for (int i = 0; i < 32; i += 8)
        dst[(size_t)(bx + ty + i) * R + by + tx] = rndtf32(t[tx][ty + i]);
}

// ---------------------------------------------------------------------------
// Round-copy (tf32 RN) for X
// ---------------------------------------------------------------------------
__global__ __launch_bounds__(256) void rnd_copy_kernel(
    const float4* __restrict__ src, float4* __restrict__ dst, int n4)
{
    const int i = blockIdx.x * 256 + threadIdx.x;
    if (i < n4) {
        float4 v = src[i];
        v.x = rndtf32(v.x); v.y = rndtf32(v.y);
        v.z = rndtf32(v.z); v.w = rndtf32(v.w);
        dst[i] = v;
    }
}

// ---------------------------------------------------------------------------
// LayerNorm over FD=256 per row, optional *(1+mask)
// ---------------------------------------------------------------------------
__global__ __launch_bounds__(256) void ln_mask_kernel(
    float* __restrict__ x, const float* __restrict__ gamma,
    const float* __restrict__ beta, const float* __restrict__ mask,
    int use_mask)
{
    const int row = blockIdx.x;
    const int f = threadIdx.x;
    const size_t base = (size_t)row * FD_;
    float v = x[base + f];

    float s = v, s2 = v * v;
    #pragma unroll
    for (int o = 16; o; o >>= 1) {
        s  += __shfl_down_sync(0xffffffffu, s,  o);
        s2 += __shfl_down_sync(0xffffffffu, s2, o);
    }
    __shared__ float rs[8], rs2[8];
    __shared__ float smu, srstd;
    const int wid = f >> 5, lane = f & 31;
    if (lane == 0) { rs[wid] = s; rs2[wid] = s2; }
    __syncthreads();
    if (f == 0) {
        float ts = 0.f, ts2 = 0.f;
        #pragma unroll
        for (int i = 0; i < 8; i++) { ts += rs[i]; ts2 += rs2[i]; }
        float mu = ts * (1.f / FD_);
        float var = ts2 * (1.f / FD_) - mu * mu;
        smu = mu;
        srstd = rsqrtf(var + 1e-5f);
    }
    __syncthreads();
    float y = (v - smu) * srstd * gamma[f] + beta[f];
    if (use_mask) y *= (1.f + mask[row >> 4]);
    x[base + f] = y;
}

// ---------------------------------------------------------------------------
// k_sum
// ---------------------------------------------------------------------------
__global__ void zero_ksum_kernel(float* __restrict__ ks)
{
    ks[blockIdx.x * FD_ + threadIdx.x] = 0.f;
}

__global__ __launch_bounds__(256) void ksum_kernel(
    const float* __restrict__ kf, float* __restrict__ ks)
{
    const int bh = blockIdx.x;
    const int chunk = blockIdx.y;
    const int b = bh >> 4, h = bh & 15;
    const int f = threadIdx.x;
    float acc = 0.f;
    const int l0 = chunk * 256;
    for (int l = l0; l < l0 + 256; ++l)
        acc += kf[((size_t)((b * L_ + l) * NH_ + h)) * FD_ + f];
    atomicAdd(&ks[bh * FD_ + f], acc);
}

// ---------------------------------------------------------------------------
// kv[bh][f][d] = sum_l k_feat * v
// ---------------------------------------------------------------------------
#define KV_BM 32
#define KV_BK 16

__global__ __launch_bounds__(256) void kv_kernel(
    const float* __restrict__ kf, const float* __restrict__ v,
    float* __restrict__ kv)
{
    const int bh = blockIdx.x;
    const int f0 = blockIdx.y * KV_BM;
    const int b = bh >> 4, h = bh & 15;
    const int tid = threadIdx.x;

    __shared__ float Ks[KV_BK][KV_BM];
    __shared__ float Vs[KV_BK][HD_];

    float acc[2][8];
    #pragma unroll
    for (int i = 0; i < 2; i++)
        #pragma unroll
        for (int j = 0; j < 8; j++) acc[i][j] = 0.f;

    const int tRow = (tid >> 4) * 2;
    const int tCol = (tid & 15) * 8;
    const int klr = tid >> 3;
    const int kfc = (tid & 7) * 4;

    for (int l0 = 0; l0 < L_; l0 += KV_BK) {
        if (tid < 128) {
            float4 a = *(const float4*)(kf +
                ((size_t)((b * L_ + l0 + klr) * NH_ + h)) * FD_ + f0 + kfc);
            Ks[klr][kfc + 0] = a.x; Ks[klr][kfc + 1] = a.y;
            Ks[klr][kfc + 2] = a.z; Ks[klr][kfc + 3] = a.w;
        }
        #pragma unroll
        for (int r = 0; r < 2; r++) {
            int idx = tid + 256 * r;
            int lr = idx >> 5, dc = (idx & 31) * 4;
            *(float4*)&Vs[lr][dc] = *(const float4*)(v +
                ((size_t)((b * L_ + l0 + lr) * NH_ + h)) * HD_ + dc);
        }
        __syncthreads();
        #pragma unroll
        for (int ll = 0; ll < KV_BK; ll++) {
            float ar[2], br[8];
            ar[0] = Ks[ll][tRow + 0];
            ar[1] = Ks[ll][tRow + 1];
            #pragma unroll
            for (int j = 0; j < 8; j++) br[j] = Vs[ll][tCol + j];
            #pragma unroll
            for (int i = 0; i < 2; i++)
                #pragma unroll
                for (int j = 0; j < 8; j++) acc[i][j] += ar[i] * br[j];
        }
        __syncthreads();
    }

    #pragma unroll
    for (int i = 0; i < 2; i++)
        #pragma unroll
        for (int j = 0; j < 8; j += 4) {
            float4 o;
            o.x = acc[i][j + 0]; o.y = acc[i][j + 1];
            o.z = acc[i][j + 2]; o.w = acc[i][j + 3];
            *(float4*)(kv + ((size_t)bh * FD_ + f0 + tRow + i) * HD_ + tCol + j) = o;
        }
}

// ---------------------------------------------------------------------------
// attn with fused denominator; output rounded to tf32 (operand of final GEMM)
// ---------------------------------------------------------------------------
#define AT_BM 64
#define AT_BK 16

__global__ __launch_bounds__(256) void attn_kernel(
    const float* __restrict__ qf, const float* __restrict__ kv,
    const float* __restrict__ ksum, float* __restrict__ out)
{
    const int bh = blockIdx.x;
    const int b = bh >> 4, h = bh & 15;
    const int l0 = blockIdx.y * AT_BM;
    const int tid = threadIdx.x;

    __shared__ float Qs[AT_BK][AT_BM];
    __shared__ float KVs[AT_BK][HD_];
    __shared__ float KSs[AT_BK];
    __shared__ float sden[AT_BM];

    float acc[4][8];
    #pragma unroll
    for (int i = 0; i < 4; i++)
        #pragma unroll
        for (int j = 0; j < 8; j++) acc[i][j] = 0.f;
    float dacc[4] = {0.f, 0.f, 0.f, 0.f};

    const int tRow = (tid >> 4) * 4;
    const int tCol = (tid & 15) * 8;
    const int qlr = tid >> 2;
    const int qfc = (tid & 3) * 4;

    for (int f0 = 0; f0 < FD_; f0 += AT_BK) {
        float4 qv = *(const float4*)(qf +
            ((size_t)((b * L_ + l0 + qlr) * NH_ + h)) * FD_ + f0 + qfc);
        Qs[qfc + 0][qlr] = qv.x; Qs[qfc + 1][qlr] = qv.y;
        Qs[qfc + 2][qlr] = qv.z; Qs[qfc + 3][qlr] = qv.w;
        #pragma unroll
        for (int r = 0; r < 2; r++) {
            int idx = tid + 256 * r;
            int fr = idx >> 5, dc = (idx & 31) * 4;
            *(float4*)&KVs[fr][dc] = *(const float4*)(kv +
                ((size_t)bh * FD_ + f0 + fr) * HD_ + dc);
        }
        if (tid < AT_BK) KSs[tid] = ksum[bh * FD_ + f0 + tid];
        __syncthreads();
        #pragma unroll
        for (int ll = 0; ll < AT_BK; ll++) {
            float ar[4], br[8];
            #pragma unroll
            for (int i = 0; i < 4; i++) ar[i] = Qs[ll][tRow + i];
            #pragma unroll
            for (int j = 0; j < 8; j++) br[j] = KVs[ll][tCol + j];
            #pragma unroll
            for (int i = 0; i < 4; i++)
                #pragma unroll
                for (int j = 0; j < 8; j++) acc[i][j] += ar[i] * br[j];
            if ((tid & 15) == 0) {
                float ksv = KSs[ll];
                #pragma unroll
                for (int i = 0; i < 4; i++) dacc[i] += ar[i] * ksv;
            }
        }
        __syncthreads();
    }

    if ((tid & 15) == 0) {
        #pragma unroll
        for (int i = 0; i < 4; i++) sden[tRow + i] = dacc[i];
    }
    __syncthreads();

    #pragma unroll
    for (int i = 0; i < 4; i++) {
        float inv = 1.f / (sden[tRow + i] + 1e-8f);
        #pragma unroll
        for (int j = 0; j < 8; j += 4) {
            float4 o;
            o.x = rndtf32(acc[i][j + 0] * inv);
            o.y = rndtf32(acc[i][j + 1] * inv);
            o.z = rndtf32(acc[i][j + 2] * inv);
            o.w = rndtf32(acc[i][j + 3] * inv);
            *(float4*)(out + ((size_t)(b * L_ + l0 + tRow + i)) * HS_ +
                       h * HD_ + tCol + j) = o;
        }
    }
}

// ---------------------------------------------------------------------------
// Host launch
// ---------------------------------------------------------------------------
extern "C" void kernel_launch(void* const* d_in, const int* in_sizes, int n_in,
                              void* d_out, int out_size)
{
    (void)in_sizes; (void)n_in; (void)out_size;
    const float* X    = (const float*)d_in[0];
    const float* mask = (const float*)d_in[1];
    const float* Wq   = (const float*)d_in[2];
    const float* bq   = (const float*)d_in[3];
    const float* Wk   = (const float*)d_in[4];
    const float* bk   = (const float*)d_in[5];
    const float* Wv   = (const float*)d_in[6];
    const float* bv   = (const float*)d_in[7];
    const float* Wo   = (const float*)d_in[8];
    const float* bo   = (const float*)d_in[9];
    const float* Wf1  = (const float*)d_in[10];
    const float* bf1  = (const float*)d_in[11];
    const float* Wf2  = (const float*)d_in[12];
    const float* bf2  = (const float*)d_in[13];
    const float* ln_g = (const float*)d_in[14];
    const float* ln_b = (const float*)d_in[15];

    float* scratch = nullptr;
    cudaGetSymbolAddress((void**)&scratch, g_scratch);
    float* q     = scratch + OFF_Q;
    float* k     = scratch + OFF_K;
    float* v     = scratch + OFF_V;
    float* tmp   = scratch + OFF_TMP;
    float* qfeat = scratch + OFF_QF;
    float* kfeat = scratch + OFF_KF;
    float* kvbuf = scratch + OFF_KV;
    float* ksbuf = scratch + OFF_KSUM;
    float* attn  = scratch + OFF_ATTN;
    float* WqT   = scratch + OFF_WQT;
    float* WkT   = scratch + OFF_WKT;
    float* WvT   = scratch + OFF_WVT;
    float* WoT   = scratch + OFF_WOT;
    float* Wf1T  = scratch + OFF_WF1T;
    float* Wf2T  = scratch + OFF_WF2T;
    float* Xr    = scratch + OFF_XR;

    static bool attr_set = false;
    if (!attr_set) {
        cudaFuncSetAttribute(gemm_tc_kernel,
                             cudaFuncAttributeMaxDynamicSharedMemorySize, GEMM_SMEM);
        attr_set = true;
    }

    dim3 t8(32, 8);
    // Weight transposes ([K,N] -> [N,K]) with tf32 RN rounding
    transpose_kernel<<<dim3(HS_/32, HS_/32), t8>>>(Wq, WqT, HS_, HS_);
    transpose_kernel<<<dim3(HS_/32, HS_/32), t8>>>(Wk, WkT, HS_, HS_);
    transpose_kernel<<<dim3(HS_/32, HS_/32), t8>>>(Wv, WvT, HS_, HS_);
    transpose_kernel<<<dim3(HS_/32, HS_/32), t8>>>(Wo, WoT, HS_, HS_);
    transpose_kernel<<<dim3(FD_/32, HD_/32), t8>>>(Wf1, Wf1T, HD_, FD_);
    transpose_kernel<<<dim3(FD_/32, FD_/32), t8>>>(Wf2, Wf2T, FD_, FD_);

    // Round X to tf32 (RN) once
    rnd_copy_kernel<<<(NROWS * HS_ / 4 + 255) / 256, 256>>>(
        (const float4*)X, (float4*)Xr, NROWS * HS_ / 4);

    dim3 blk(256);
    dim3 gBig(HS_ / 128, NROWS / 128);   // (16, 64)
    dim3 gF(FD_ / 128, NTOK / 128);      // (2, 1024)

    // QKV projections (q,k rounded: they feed the feature GEMMs)
    gemm_tc_kernel<<<gBig, blk, GEMM_SMEM>>>(Xr, WqT, bq, q, NROWS, HS_, HS_, 0, 1);
    gemm_tc_kernel<<<gBig, blk, GEMM_SMEM>>>(Xr, WkT, bk, k, NROWS, HS_, HS_, 0, 1);
    gemm_tc_kernel<<<gBig, blk, GEMM_SMEM>>>(Xr, WvT, bv, v, NROWS, HS_, HS_, 0, 0);

    // feature_map(q)
    gemm_tc_kernel<<<gF, blk, GEMM_SMEM>>>(q, Wf1T, bf1, tmp, NTOK, FD_, HD_, 1, 1);
    gemm_tc_kernel<<<gF, blk, GEMM_SMEM>>>(tmp, Wf2T, bf2, qfeat, NTOK, FD_, FD_, 0, 0);
    ln_mask_kernel<<<NTOK, 256>>>(qfeat, ln_g, ln_b, mask, 0);

    // feature_map(k) * (1 + mask)
    gemm_tc_kernel<<<gF, blk, GEMM_SMEM>>>(k, Wf1T, bf1, tmp, NTOK, FD_, HD_, 1, 1);
    gemm_tc_kernel<<<gF, blk, GEMM_SMEM>>>(tmp, Wf2T, bf2, kfeat, NTOK, FD_, FD_, 0, 0);
    ln_mask_kernel<<<NTOK, 256>>>(kfeat, ln_g, ln_b, mask, 1);

    // k_sum
    zero_ksum_kernel<<<B_ * NH_, 256>>>(ksbuf);
    ksum_kernel<<<dim3(B_ * NH_, 16), 256>>>(kfeat, ksbuf);

    // kv
    kv_kernel<<<dim3(B_ * NH_, FD_ / KV_BM), 256>>>(kfeat, v, kvbuf);

    // attn (output rounded: operand of final GEMM)
    attn_kernel<<<dim3(B_ * NH_, L_ / AT_BM), 256>>>(qfeat, kvbuf, ksbuf, attn);

    // output projection
    gemm_tc_kernel<<<gBig, blk, GEMM_SMEM>>>(attn, WoT, bo, (float*)d_out,
                                             NROWS, HS_, HS_, 0, 0);
}

// round 8
// speedup vs baseline: 3.5350x; 1.3165x over previous
#include <cuda_runtime.h>
#include <cuda_fp16.h>
#include <cstdint>

// Problem constants
#define B_  2
#define L_  4096
#define HS_ 2048
#define NH_ 16
#define HD_ 128
#define FD_ 256
#define NROWS (B_*L_)            // 8192
#define NTOK  (B_*L_*NH_)        // 131072

// Scratch layout (float units; half buffers reinterpret these regions)
#define OFF_Q    ((size_t)0)
#define OFF_K    ((size_t)16777216)
#define OFF_V    ((size_t)33554432)
#define OFF_TMP  ((size_t)50331648)
#define OFF_QF   ((size_t)83886080)
#define OFF_KF   ((size_t)117440512)
#define OFF_KV   ((size_t)150994944)
#define OFF_KSUM ((size_t)152043520)
#define OFF_ATTN ((size_t)152051712)
#define OFF_WQT  ((size_t)168828928)
#define OFF_WKT  (OFF_WQT + 4194304)
#define OFF_WVT  (OFF_WKT + 4194304)
#define OFF_WOT  (OFF_WVT + 4194304)
#define OFF_WF1T (OFF_WOT + 4194304)
#define OFF_WF2T (OFF_WF1T + 32768)
#define OFF_XR   (OFF_WF2T + 65536)
#define SCRATCH_TOTAL (OFF_XR + 16777216)

__device__ float g_scratch[SCRATCH_TOTAL];

// ---------------------------------------------------------------------------
// Helpers
// ---------------------------------------------------------------------------
__device__ __forceinline__ uint32_t smem_u32(const void* p) {
    uint32_t a;
    asm("{ .reg .u64 t; cvta.to.shared.u64 t, %1; cvt.u32.u64 %0, t; }"
        : "=r"(a) : "l"(p));
    return a;
}

#define CP_ASYNC16(saddr, gaddr) \
    asm volatile("cp.async.cg.shared.global [%0], [%1], 16;" \
                 :: "r"(saddr), "l"(gaddr))
#define CP_COMMIT() asm volatile("cp.async.commit_group;")

#define LDSM4(r, addr) \
    asm volatile("ldmatrix.sync.aligned.m8n8.x4.shared.b16 {%0,%1,%2,%3}, [%4];" \
                 : "=r"((r)[0]), "=r"((r)[1]), "=r"((r)[2]), "=r"((r)[3]) \
                 : "r"(addr))

__device__ __forceinline__ void mma_f16(float* d, const uint32_t* a,
                                        uint32_t b0, uint32_t b1) {
    asm volatile(
        "mma.sync.aligned.m16n8k16.row.col.f32.f16.f16.f32 "
        "{%0,%1,%2,%3}, {%4,%5,%6,%7}, {%8,%9}, {%0,%1,%2,%3};"
        : "+f"(d[0]), "+f"(d[1]), "+f"(d[2]), "+f"(d[3])
        : "r"(a[0]), "r"(a[1]), "r"(a[2]), "r"(a[3]), "r"(b0), "r"(b1));
}

// ---------------------------------------------------------------------------
// fp16 tensor-core GEMM (f32 accum): C = A[M,K] @ BT[N,K]^T + bias, opt relu.
// CTA 128x128, BK=32 (half), 8 warps (32x64 each), 3-stage cp.async,
// ldmatrix.x4 fragment loads. SMEM rows padded to 80B -> conflict-free.
// ---------------------------------------------------------------------------
#define HROW_B   80                       // bytes per padded row (32 half + pad)
#define A_BYTES  (128 * HROW_B)           // 10240
#define STAGE_BYTES (2 * A_BYTES)         // 20480
#define GEMM_SMEM (3 * STAGE_BYTES)       // 61440

__global__ __launch_bounds__(256, 2) void gemm_h_kernel(
    const __half* __restrict__ A, const __half* __restrict__ BT,
    const float* __restrict__ bias, void* __restrict__ Cout,
    int M, int N, int K, int relu, int out_half)
{
    extern __shared__ char smraw[];
    const uint32_t sbase = smem_u32(smraw);
    const int tid = threadIdx.x;
    const int wid = tid >> 5, lane = tid & 31;
    const int wm = wid & 3, wn = wid >> 2;      // 4 (M) x 2 (N) warps
    const int gid = lane >> 2, tig = lane & 3;
    const int n0 = blockIdx.x * 128, m0 = blockIdx.y * 128;

    float acc[2][8][4];
    #pragma unroll
    for (int mi = 0; mi < 2; mi++)
        #pragma unroll
        for (int ni = 0; ni < 8; ni++)
            #pragma unroll
            for (int j = 0; j < 4; j++) acc[mi][ni][j] = 0.f;

    const int nchunk = K >> 5;

    auto issue_chunk = [&](int c, int slot) {
        const __half* Ag = A + (size_t)m0 * K + c * 32;
        const __half* Bg = BT + (size_t)n0 * K + c * 32;
        const uint32_t sA = sbase + (uint32_t)slot * STAGE_BYTES;
        const uint32_t sB = sA + A_BYTES;
        #pragma unroll
        for (int r = 0; r < 2; r++) {
            const int idx = tid + 256 * r;        // 0..511
            const int row = idx >> 2, seg = idx & 3;
            const uint32_t so = (uint32_t)(row * HROW_B + seg * 16);
            CP_ASYNC16(sA + so, Ag + (size_t)row * K + seg * 8);
            CP_ASYNC16(sB + so, Bg + (size_t)row * K + seg * 8);
        }
    };

    issue_chunk(0, 0); CP_COMMIT();
    issue_chunk(1, 1); CP_COMMIT();

    const int l15 = lane & 15;
    const int koff = (lane >> 4) * 16;          // byte offset for hi-k half

    int slot = 0;
    for (int c = 0; c < nchunk; c++) {
        if (c + 2 < nchunk) issue_chunk(c + 2, (c + 2) % 3);
        CP_COMMIT();                             // possibly empty group
        asm volatile("cp.async.wait_group 2;");
        __syncthreads();

        const uint32_t sA = sbase + (uint32_t)slot * STAGE_BYTES;
        const uint32_t sB = sA + A_BYTES;

        #pragma unroll
        for (int ks = 0; ks < 2; ks++) {
            uint32_t a[2][4];
            #pragma unroll
            for (int mi = 0; mi < 2; mi++) {
                const uint32_t addr = sA +
                    (uint32_t)((wm * 32 + mi * 16 + l15) * HROW_B + ks * 32 + koff);
                LDSM4(a[mi], addr);
            }
            uint32_t bf[4][4];
            #pragma unroll
            for (int g = 0; g < 4; g++) {
                const uint32_t addr = sB +
                    (uint32_t)((wn * 64 + g * 16 + l15) * HROW_B + ks * 32 + koff);
                LDSM4(bf[g], addr);
            }
            #pragma unroll
            for (int g = 0; g < 4; g++) {
                #pragma unroll
                for (int h = 0; h < 2; h++) {
                    const uint32_t b0 = bf[g][h];       // k lo
                    const uint32_t b1 = bf[g][h + 2];   // k hi
                    mma_f16(acc[0][g * 2 + h], a[0], b0, b1);
                    mma_f16(acc[1][g * 2 + h], a[1], b0, b1);
                }
            }
        }
        __syncthreads();
        slot++; if (slot == 3) slot = 0;
    }

    // Epilogue
    #pragma unroll
    for (int mi = 0; mi < 2; mi++) {
        const int row = m0 + wm * 32 + mi * 16 + gid;
        #pragma unroll
        for (int ni = 0; ni < 8; ni++) {
            const int col = n0 + wn * 64 + ni * 8 + tig * 2;
            const float b0v = bias[col], b1v = bias[col + 1];
            float v0 = acc[mi][ni][0] + b0v;
            float v1 = acc[mi][ni][1] + b1v;
            float v2 = acc[mi][ni][2] + b0v;
            float v3 = acc[mi][ni][3] + b1v;
            if (relu) {
                v0 = fmaxf(v0, 0.f); v1 = fmaxf(v1, 0.f);
                v2 = fmaxf(v2, 0.f); v3 = fmaxf(v3, 0.f);
            }
            if (out_half) {
                __half* Ch = (__half*)Cout;
                *(__half2*)(Ch + (size_t)row * N + col) = __floats2half2_rn(v0, v1);
                *(__half2*)(Ch + (size_t)(row + 8) * N + col) = __floats2half2_rn(v2, v3);
            } else {
                float* Cf = (float*)Cout;
                float2 o01; o01.x = v0; o01.y = v1;
                float2 o23; o23.x = v2; o23.y = v3;
                *(float2*)(Cf + (size_t)row * N + col) = o01;
                *(float2*)(Cf + (size_t)(row + 8) * N + col) = o23;
            }
        }
    }
}

// ---------------------------------------------------------------------------
// Transpose to half: dst[C,R] = half(src[R,C]^T)
// ---------------------------------------------------------------------------
__global__ __launch_bounds__(256) void transpose_h_kernel(
    const float* __restrict__ src, __half* __restrict__ dst, int R, int C)
{
    __shared__ float t[32][33];
    const int bx = blockIdx.x * 32;
    const int by = blockIdx.y * 32;
    const int tx = threadIdx.x, ty = threadIdx.y;
    #pragma unroll
    for (int i = 0; i < 32; i += 8)
        t[ty + i][tx] = src[(size_t)(by + ty + i) * C + bx + tx];
    __syncthreads();
    #pragma unroll
    for (int i = 0; i < 32; i += 8)
        dst[(size_t)(bx + ty + i) * R + by + tx] = __float2half_rn(t[tx][ty + i]);
}

// ---------------------------------------------------------------------------
// float -> half copy for X
// ---------------------------------------------------------------------------
__global__ __launch_bounds__(256) void f2h_kernel(
    const float4* __restrict__ src, uint2* __restrict__ dst, int n4)
{
    const int i = blockIdx.x * 256 + threadIdx.x;
    if (i < n4) {
        float4 v = src[i];
        __half2 a = __floats2half2_rn(v.x, v.y);
        __half2 b = __floats2half2_rn(v.z, v.w);
        uint2 o;
        o.x = *(uint32_t*)&a;
        o.y = *(uint32_t*)&b;
        dst[i] = o;
    }
}

// ---------------------------------------------------------------------------
// LayerNorm over FD=256 per row, optional *(1+mask)
// ---------------------------------------------------------------------------
__global__ __launch_bounds__(256) void ln_mask_kernel(
    float* __restrict__ x, const float* __restrict__ gamma,
    const float* __restrict__ beta, const float* __restrict__ mask,
    int use_mask)
{
    const int row = blockIdx.x;
    const int f = threadIdx.x;
    const size_t base = (size_t)row * FD_;
    float v = x[base + f];

    float s = v, s2 = v * v;
    #pragma unroll
    for (int o = 16; o; o >>= 1) {
        s  += __shfl_down_sync(0xffffffffu, s,  o);
        s2 += __shfl_down_sync(0xffffffffu, s2, o);
    }
    __shared__ float rs[8], rs2[8];
    __shared__ float smu, srstd;
    const int wid = f >> 5, lane = f & 31;
    if (lane == 0) { rs[wid] = s; rs2[wid] = s2; }
    __syncthreads();
    if (f == 0) {
        float ts = 0.f, ts2 = 0.f;
        #pragma unroll
        for (int i = 0; i < 8; i++) { ts += rs[i]; ts2 += rs2[i]; }
        float mu = ts * (1.f / FD_);
        float var = ts2 * (1.f / FD_) - mu * mu;
        smu = mu;
        srstd = rsqrtf(var + 1e-5f);
    }
    __syncthreads();
    float y = (v - smu) * srstd * gamma[f] + beta[f];
    if (use_mask) y *= (1.f + mask[row >> 4]);
    x[base + f] = y;
}

// ---------------------------------------------------------------------------
// k_sum
// ---------------------------------------------------------------------------
__global__ void zero_ksum_kernel(float* __restrict__ ks)
{
    ks[blockIdx.x * FD_ + threadIdx.x] = 0.f;
}

__global__ __launch_bounds__(256) void ksum_kernel(
    const float* __restrict__ kf, float* __restrict__ ks)
{
    const int bh = blockIdx.x;
    const int chunk = blockIdx.y;
    const int b = bh >> 4, h = bh & 15;
    const int f = threadIdx.x;
    float acc = 0.f;
    const int l0 = chunk * 256;
    for (int l = l0; l < l0 + 256; ++l)
        acc += kf[((size_t)((b * L_ + l) * NH_ + h)) * FD_ + f];
    atomicAdd(&ks[bh * FD_ + f], acc);
}

// ---------------------------------------------------------------------------
// kv[bh][f][d] = sum_l k_feat * v
// ---------------------------------------------------------------------------
#define KV_BM 32
#define KV_BK 16

__global__ __launch_bounds__(256) void kv_kernel(
    const float* __restrict__ kf, const float* __restrict__ v,
    float* __restrict__ kv)
{
    const int bh = blockIdx.x;
    const int f0 = blockIdx.y * KV_BM;
    const int b = bh >> 4, h = bh & 15;
    const int tid = threadIdx.x;

    __shared__ float Ks[KV_BK][KV_BM];
    __shared__ float Vs[KV_BK][HD_];

    float acc[2][8];
    #pragma unroll
    for (int i = 0; i < 2; i++)
        #pragma unroll
        for (int j = 0; j < 8; j++) acc[i][j] = 0.f;

    const int tRow = (tid >> 4) * 2;
    const int tCol = (tid & 15) * 8;
    const int klr = tid >> 3;
    const int kfc = (tid & 7) * 4;

    for (int l0 = 0; l0 < L_; l0 += KV_BK) {
        if (tid < 128) {
            float4 a = *(const float4*)(kf +
                ((size_t)((b * L_ + l0 + klr) * NH_ + h)) * FD_ + f0 + kfc);
            Ks[klr][kfc + 0] = a.x; Ks[klr][kfc + 1] = a.y;
            Ks[klr][kfc + 2] = a.z; Ks[klr][kfc + 3] = a.w;
        }
        #pragma unroll
        for (int r = 0; r < 2; r++) {
            int idx = tid + 256 * r;
            int lr = idx >> 5, dc = (idx & 31) * 4;
            *(float4*)&Vs[lr][dc] = *(const float4*)(v +
                ((size_t)((b * L_ + l0 + lr) * NH_ + h)) * HD_ + dc);
        }
        __syncthreads();
        #pragma unroll
        for (int ll = 0; ll < KV_BK; ll++) {
            float ar[2], br[8];
            ar[0] = Ks[ll][tRow + 0];
            ar[1] = Ks[ll][tRow + 1];
            #pragma unroll
            for (int j = 0; j < 8; j++) br[j] = Vs[ll][tCol + j];
            #pragma unroll
            for (int i = 0; i < 2; i++)
                #pragma unroll
                for (int j = 0; j < 8; j++) acc[i][j] += ar[i] * br[j];
        }
        __syncthreads();
    }

    #pragma unroll
    for (int i = 0; i < 2; i++)
        #pragma unroll
        for (int j = 0; j < 8; j += 4) {
            float4 o;
            o.x = acc[i][j + 0]; o.y = acc[i][j + 1];
            o.z = acc[i][j + 2]; o.w = acc[i][j + 3];
            *(float4*)(kv + ((size_t)bh * FD_ + f0 + tRow + i) * HD_ + tCol + j) = o;
        }
}

// ---------------------------------------------------------------------------
// attn with fused denominator; output as half (operand of final GEMM)
// ---------------------------------------------------------------------------
#define AT_BM 64
#define AT_BK 16

__global__ __launch_bounds__(256) void attn_kernel(
    const float* __restrict__ qf, const float* __restrict__ kv,
    const float* __restrict__ ksum, __half* __restrict__ out)
{
    const int bh = blockIdx.x;
    const int b = bh >> 4, h = bh & 15;
    const int l0 = blockIdx.y * AT_BM;
    const int tid = threadIdx.x;

    __shared__ float Qs[AT_BK][AT_BM];
    __shared__ float KVs[AT_BK][HD_];
    __shared__ float KSs[AT_BK];
    __shared__ float sden[AT_BM];

    float acc[4][8];
    #pragma unroll
    for (int i = 0; i < 4; i++)
        #pragma unroll
        for (int j = 0; j < 8; j++) acc[i][j] = 0.f;
    float dacc[4] = {0.f, 0.f, 0.f, 0.f};

    const int tRow = (tid >> 4) * 4;
    const int tCol = (tid & 15) * 8;
    const int qlr = tid >> 2;
    const int qfc = (tid & 3) * 4;

    for (int f0 = 0; f0 < FD_; f0 += AT_BK) {
        float4 qv = *(const float4*)(qf +
            ((size_t)((b * L_ + l0 + qlr) * NH_ + h)) * FD_ + f0 + qfc);
        Qs[qfc + 0][qlr] = qv.x; Qs[qfc + 1][qlr] = qv.y;
        Qs[qfc + 2][qlr] = qv.z; Qs[qfc + 3][qlr] = qv.w;
        #pragma unroll
        for (int r = 0; r < 2; r++) {
            int idx = tid + 256 * r;
            int fr = idx >> 5, dc = (idx & 31) * 4;
            *(float4*)&KVs[fr][dc] = *(const float4*)(kv +
                ((size_t)bh * FD_ + f0 + fr) * HD_ + dc);
        }
        if (tid < AT_BK) KSs[tid] = ksum[bh * FD_ + f0 + tid];
        __syncthreads();
        #pragma unroll
        for (int ll = 0; ll < AT_BK; ll++) {
            float ar[4], br[8];
            #pragma unroll
            for (int i = 0; i < 4; i++) ar[i] = Qs[ll][tRow + i];
            #pragma unroll
            for (int j = 0; j < 8; j++) br[j] = KVs[ll][tCol + j];
            #pragma unroll
            for (int i = 0; i < 4; i++)
                #pragma unroll
                for (int j = 0; j < 8; j++) acc[i][j] += ar[i] * br[j];
            if ((tid & 15) == 0) {
                float ksv = KSs[ll];
                #pragma unroll
                for (int i = 0; i < 4; i++) dacc[i] += ar[i] * ksv;
            }
        }
        __syncthreads();
    }

    if ((tid & 15) == 0) {
        #pragma unroll
        for (int i = 0; i < 4; i++) sden[tRow + i] = dacc[i];
    }
    __syncthreads();

    #pragma unroll
    for (int i = 0; i < 4; i++) {
        float inv = 1.f / (sden[tRow + i] + 1e-8f);
        #pragma unroll
        for (int j = 0; j < 8; j += 4) {
            __half2 p0 = __floats2half2_rn(acc[i][j + 0] * inv, acc[i][j + 1] * inv);
            __half2 p1 = __floats2half2_rn(acc[i][j + 2] * inv, acc[i][j + 3] * inv);
            uint2 o;
            o.x = *(uint32_t*)&p0;
            o.y = *(uint32_t*)&p1;
            *(uint2*)(out + ((size_t)(b * L_ + l0 + tRow + i)) * HS_ +
                      h * HD_ + tCol + j) = o;
        }
    }
}

// ---------------------------------------------------------------------------
// Host launch
// ---------------------------------------------------------------------------
extern "C" void kernel_launch(void* const* d_in, const int* in_sizes, int n_in,
                              void* d_out, int out_size)
{
    (void)in_sizes; (void)n_in; (void)out_size;
    const float* X    = (const float*)d_in[0];
    const float* mask = (const float*)d_in[1];
    const float* Wq   = (const float*)d_in[2];
    const float* bq   = (const float*)d_in[3];
    const float* Wk   = (const float*)d_in[4];
    const float* bk   = (const float*)d_in[5];
    const float* Wv   = (const float*)d_in[6];
    const float* bv   = (const float*)d_in[7];
    const float* Wo   = (const float*)d_in[8];
    const float* bo   = (const float*)d_in[9];
    const float* Wf1  = (const float*)d_in[10];
    const float* bf1  = (const float*)d_in[11];
    const float* Wf2  = (const float*)d_in[12];
    const float* bf2  = (const float*)d_in[13];
    const float* ln_g = (const float*)d_in[14];
    const float* ln_b = (const float*)d_in[15];

    float* scratch = nullptr;
    cudaGetSymbolAddress((void**)&scratch, g_scratch);
    __half* qh    = (__half*)(scratch + OFF_Q);
    __half* kh    = (__half*)(scratch + OFF_K);
    float*  v     = scratch + OFF_V;
    __half* tmph  = (__half*)(scratch + OFF_TMP);
    float*  qfeat = scratch + OFF_QF;
    float*  kfeat = scratch + OFF_KF;
    float*  kvbuf = scratch + OFF_KV;
    float*  ksbuf = scratch + OFF_KSUM;
    __half* attnh = (__half*)(scratch + OFF_ATTN);
    __half* WqT   = (__half*)(scratch + OFF_WQT);
    __half* WkT   = (__half*)(scratch + OFF_WKT);
    __half* WvT   = (__half*)(scratch + OFF_WVT);
    __half* WoT   = (__half*)(scratch + OFF_WOT);
    __half* Wf1T  = (__half*)(scratch + OFF_WF1T);
    __half* Wf2T  = (__half*)(scratch + OFF_WF2T);
    __half* Xh    = (__half*)(scratch + OFF_XR);

    static bool attr_set = false;
    if (!attr_set) {
        cudaFuncSetAttribute(gemm_h_kernel,
                             cudaFuncAttributeMaxDynamicSharedMemorySize, GEMM_SMEM);
        attr_set = true;
    }

    dim3 t8(32, 8);
    // Weight transposes ([K,N] -> [N,K]) with fp16 RN conversion
    transpose_h_kernel<<<dim3(HS_/32, HS_/32), t8>>>(Wq, WqT, HS_, HS_);
    transpose_h_kernel<<<dim3(HS_/32, HS_/32), t8>>>(Wk, WkT, HS_, HS_);
    transpose_h_kernel<<<dim3(HS_/32, HS_/32), t8>>>(Wv, WvT, HS_, HS_);
    transpose_h_kernel<<<dim3(HS_/32, HS_/32), t8>>>(Wo, WoT, HS_, HS_);
    transpose_h_kernel<<<dim3(FD_/32, HD_/32), t8>>>(Wf1, Wf1T, HD_, FD_);
    transpose_h_kernel<<<dim3(FD_/32, FD_/32), t8>>>(Wf2, Wf2T, FD_, FD_);

    // X -> fp16 once
    f2h_kernel<<<(NROWS * HS_ / 4 + 255) / 256, 256>>>(
        (const float4*)X, (uint2*)Xh, NROWS * HS_ / 4);

    dim3 blk(256);
    dim3 gBig(HS_ / 128, NROWS / 128);   // (16, 64)
    dim3 gF(FD_ / 128, NTOK / 128);      // (2, 1024)

    // QKV projections (q,k as half -> feed feature GEMMs; v as float)
    gemm_h_kernel<<<gBig, blk, GEMM_SMEM>>>(Xh, WqT, bq, qh, NROWS, HS_, HS_, 0, 1);
    gemm_h_kernel<<<gBig, blk, GEMM_SMEM>>>(Xh, WkT, bk, kh, NROWS, HS_, HS_, 0, 1);
    gemm_h_kernel<<<gBig, blk, GEMM_SMEM>>>(Xh, WvT, bv, v,  NROWS, HS_, HS_, 0, 0);

    // feature_map(q)
    gemm_h_kernel<<<gF, blk, GEMM_SMEM>>>(qh, Wf1T, bf1, tmph, NTOK, FD_, HD_, 1, 1);
    gemm_h_kernel<<<gF, blk, GEMM_SMEM>>>(tmph, Wf2T, bf2, qfeat, NTOK, FD_, FD_, 0, 0);
    ln_mask_kernel<<<NTOK, 256>>>(qfeat, ln_g, ln_b, mask, 0);

    // feature_map(k) * (1 + mask)
    gemm_h_kernel<<<gF, blk, GEMM_SMEM>>>(kh, Wf1T, bf1, tmph, NTOK, FD_, HD_, 1, 1);
    gemm_h_kernel<<<gF, blk, GEMM_SMEM>>>(tmph, Wf2T, bf2, kfeat, NTOK, FD_, FD_, 0, 0);
    ln_mask_kernel<<<NTOK, 256>>>(kfeat, ln_g, ln_b, mask, 1);

    // k_sum
    zero_ksum_kernel<<<B_ * NH_, 256>>>(ksbuf);
    ksum_kernel<<<dim3(B_ * NH_, 16), 256>>>(kfeat, ksbuf);

    // kv
    kv_kernel<<<dim3(B_ * NH_, FD_ / KV_BM), 256>>>(kfeat, v, kvbuf);

    // attn -> half (operand of final GEMM)
    attn_kernel<<<dim3(B_ * NH_, L_ / AT_BM), 256>>>(qfeat, kvbuf, ksbuf, attnh);

    // output projection (float out to d_out)
    gemm_h_kernel<<<gBig, blk, GEMM_SMEM>>>(attnh, WoT, bo, (float*)d_out,
                                            NROWS, HS_, HS_, 0, 0);
}

// round 9
// speedup vs baseline: 6.2007x; 1.7541x over previous
#include <cuda_runtime.h>
#include <cuda_fp16.h>
#include <cstdint>

// Problem constants
#define B_  2
#define L_  4096
#define HS_ 2048
#define NH_ 16
#define HD_ 128
#define FD_ 256
#define NROWS (B_*L_)            // 8192
#define NTOK  (B_*L_*NH_)        // 131072
#define BH_   (B_*NH_)           // 32

// Scratch layout (float units)
#define OFF_XH    ((size_t)0)                       // X half: 8.4M fl
#define OFF_QH    ((size_t)9437184)
#define OFF_KH    ((size_t)18874368)
#define OFF_VH    ((size_t)28311552)
#define OFF_TMPH  ((size_t)37748736)                // tmp half [NTOK][256]
#define OFF_QFH   ((size_t)56623104)                // qf half [32][4096][256]
#define OFF_KFH   ((size_t)75497472)
#define OFF_KVP   ((size_t)94371840)                // fp32 partials [8][32][128][256]
#define OFF_KVT   ((size_t)103809024)               // kvT half [32][128][256]
#define OFF_KSUM  ((size_t)104857600)               // fp32 [32][256]
#define OFF_DEN   ((size_t)104873984)               // fp32 [32][4096]
#define OFF_ATTNH ((size_t)105906176)               // half [8192][2048]
#define OFF_WQT   ((size_t)115343360)
#define OFF_WKT   (OFF_WQT + 2097152)
#define OFF_WVT   (OFF_WKT + 2097152)
#define OFF_WOT   (OFF_WVT + 2097152)
#define OFF_WF1T  (OFF_WOT + 2097152)
#define OFF_WF2T  (OFF_WF1T + 16384)
#define SCRATCH_TOTAL (OFF_WF2T + 32768 + 1024)

__device__ float g_scratch[SCRATCH_TOTAL];

// ---------------------------------------------------------------------------
// Helpers
// ---------------------------------------------------------------------------
__device__ __forceinline__ uint32_t smem_u32(const void* p) {
    uint32_t a;
    asm("{ .reg .u64 t; cvta.to.shared.u64 t, %1; cvt.u32.u64 %0, t; }"
        : "=r"(a) : "l"(p));
    return a;
}

#define CP_ASYNC16(saddr, gaddr) \
    asm volatile("cp.async.cg.shared.global [%0], [%1], 16;" \
                 :: "r"(saddr), "l"(gaddr))
#define CP_COMMIT() asm volatile("cp.async.commit_group;")

#define LDSM4(r, addr) \
    asm volatile("ldmatrix.sync.aligned.m8n8.x4.shared.b16 {%0,%1,%2,%3}, [%4];" \
                 : "=r"((r)[0]), "=r"((r)[1]), "=r"((r)[2]), "=r"((r)[3]) \
                 : "r"(addr))

#define LDSM4T(r, addr) \
    asm volatile("ldmatrix.sync.aligned.m8n8.x4.trans.shared.b16 {%0,%1,%2,%3}, [%4];" \
                 : "=r"((r)[0]), "=r"((r)[1]), "=r"((r)[2]), "=r"((r)[3]) \
                 : "r"(addr))

__device__ __forceinline__ void mma_f16(float* d, const uint32_t* a,
                                        uint32_t b0, uint32_t b1) {
    asm volatile(
        "mma.sync.aligned.m16n8k16.row.col.f32.f16.f16.f32 "
        "{%0,%1,%2,%3}, {%4,%5,%6,%7}, {%8,%9}, {%0,%1,%2,%3};"
        : "+f"(d[0]), "+f"(d[1]), "+f"(d[2]), "+f"(d[3])
        : "r"(a[0]), "r"(a[1]), "r"(a[2]), "r"(a[3]), "r"(b0), "r"(b1));
}

// ---------------------------------------------------------------------------
// fp16 tensor GEMM (validated): C = A[M,K]@BT[N,K]^T + bias, opt relu/half out
// CTA 128x128, BK=32, 8 warps (32x64), 3-stage cp.async.
// ---------------------------------------------------------------------------
#define HROW_B   80
#define A_BYTES  (128 * HROW_B)
#define STAGE_BYTES (2 * A_BYTES)
#define GEMM_SMEM (3 * STAGE_BYTES)

__global__ __launch_bounds__(256, 2) void gemm_h_kernel(
    const __half* __restrict__ A, const __half* __restrict__ BT,
    const float* __restrict__ bias, void* __restrict__ Cout,
    int M, int N, int K, int relu, int out_half)
{
    extern __shared__ char smraw[];
    const uint32_t sbase = smem_u32(smraw);
    const int tid = threadIdx.x;
    const int wid = tid >> 5, lane = tid & 31;
    const int wm = wid & 3, wn = wid >> 2;
    const int gid = lane >> 2, tig = lane & 3;
    const int n0 = blockIdx.x * 128, m0 = blockIdx.y * 128;

    float acc[2][8][4];
    #pragma unroll
    for (int mi = 0; mi < 2; mi++)
        #pragma unroll
        for (int ni = 0; ni < 8; ni++)
            #pragma unroll
            for (int j = 0; j < 4; j++) acc[mi][ni][j] = 0.f;

    const int nchunk = K >> 5;

    auto issue_chunk = [&](int c, int slot) {
        const __half* Ag = A + (size_t)m0 * K + c * 32;
        const __half* Bg = BT + (size_t)n0 * K + c * 32;
        const uint32_t sA = sbase + (uint32_t)slot * STAGE_BYTES;
        const uint32_t sB = sA + A_BYTES;
        #pragma unroll
        for (int r = 0; r < 2; r++) {
            const int idx = tid + 256 * r;
            const int row = idx >> 2, seg = idx & 3;
            const uint32_t so = (uint32_t)(row * HROW_B + seg * 16);
            CP_ASYNC16(sA + so, Ag + (size_t)row * K + seg * 8);
            CP_ASYNC16(sB + so, Bg + (size_t)row * K + seg * 8);
        }
    };

    issue_chunk(0, 0); CP_COMMIT();
    issue_chunk(1, 1); CP_COMMIT();

    const int l15 = lane & 15;
    const int koff = (lane >> 4) * 16;

    int slot = 0;
    for (int c = 0; c < nchunk; c++) {
        if (c + 2 < nchunk) issue_chunk(c + 2, (c + 2) % 3);
        CP_COMMIT();
        asm volatile("cp.async.wait_group 2;");
        __syncthreads();

        const uint32_t sA = sbase + (uint32_t)slot * STAGE_BYTES;
        const uint32_t sB = sA + A_BYTES;

        #pragma unroll
        for (int ks = 0; ks < 2; ks++) {
            uint32_t a[2][4];
            #pragma unroll
            for (int mi = 0; mi < 2; mi++)
                LDSM4(a[mi], sA + (uint32_t)((wm * 32 + mi * 16 + l15) * HROW_B + ks * 32 + koff));
            uint32_t bf[4][4];
            #pragma unroll
            for (int g = 0; g < 4; g++)
                LDSM4(bf[g], sB + (uint32_t)((wn * 64 + g * 16 + l15) * HROW_B + ks * 32 + koff));
            #pragma unroll
            for (int g = 0; g < 4; g++)
                #pragma unroll
                for (int h = 0; h < 2; h++) {
                    mma_f16(acc[0][g * 2 + h], a[0], bf[g][h], bf[g][h + 2]);
                    mma_f16(acc[1][g * 2 + h], a[1], bf[g][h], bf[g][h + 2]);
                }
        }
        __syncthreads();
        slot++; if (slot == 3) slot = 0;
    }

    #pragma unroll
    for (int mi = 0; mi < 2; mi++) {
        const int row = m0 + wm * 32 + mi * 16 + gid;
        #pragma unroll
        for (int ni = 0; ni < 8; ni++) {
            const int col = n0 + wn * 64 + ni * 8 + tig * 2;
            const float b0v = bias[col], b1v = bias[col + 1];
            float v0 = acc[mi][ni][0] + b0v;
            float v1 = acc[mi][ni][1] + b1v;
            float v2 = acc[mi][ni][2] + b0v;
            float v3 = acc[mi][ni][3] + b1v;
            if (relu) {
                v0 = fmaxf(v0, 0.f); v1 = fmaxf(v1, 0.f);
                v2 = fmaxf(v2, 0.f); v3 = fmaxf(v3, 0.f);
            }
            if (out_half) {
                __half* Ch = (__half*)Cout;
                *(__half2*)(Ch + (size_t)row * N + col) = __floats2half2_rn(v0, v1);
                *(__half2*)(Ch + (size_t)(row + 8) * N + col) = __floats2half2_rn(v2, v3);
            } else {
                float* Cf = (float*)Cout;
                float2 o01; o01.x = v0; o01.y = v1;
                float2 o23; o23.x = v2; o23.y = v3;
                *(float2*)(Cf + (size_t)row * N + col) = o01;
                *(float2*)(Cf + (size_t)(row + 8) * N + col) = o23;
            }
        }
    }
}

// ---------------------------------------------------------------------------
// Wf2 GEMM with fused LayerNorm + mask + head-major half output.
// CTA 128 (tok rows) x 256 (full FD). Warps: 2 (M) x 4 (N), warp tile 64x64.
// out[(b*NH+h)*L + l][f] half.
// ---------------------------------------------------------------------------
#define LNA_BYTES (128 * HROW_B)            // 10240
#define LNB_BYTES (256 * HROW_B)            // 20480
#define LN_STAGE  (LNA_BYTES + LNB_BYTES)   // 30720
#define LN_SMEM   (2 * LN_STAGE)            // 61440

__global__ __launch_bounds__(256, 1) void gemm_ln_kernel(
    const __half* __restrict__ A, const __half* __restrict__ BT,
    const float* __restrict__ bias, const float* __restrict__ gamma,
    const float* __restrict__ beta, const float* __restrict__ mask,
    __half* __restrict__ out, int use_mask)
{
    extern __shared__ char smraw[];
    const uint32_t sbase = smem_u32(smraw);
    float* smf = (float*)smraw;
    const int tid = threadIdx.x;
    const int wid = tid >> 5, lane = tid & 31;
    const int wm = wid & 1, wn = wid >> 1;      // 2 (M) x 4 (N)
    const int gid = lane >> 2, tig = lane & 3;
    const int m0 = blockIdx.x * 128;
    const int K = FD_;

    float acc[4][8][4];
    #pragma unroll
    for (int mi = 0; mi < 4; mi++)
        #pragma unroll
        for (int ni = 0; ni < 8; ni++)
            #pragma unroll
            for (int j = 0; j < 4; j++) acc[mi][ni][j] = 0.f;

    auto issue_chunk = [&](int c, int slot) {
        const __half* Ag = A + (size_t)m0 * K + c * 32;
        const __half* Bg = BT + c * 32;
        const uint32_t sA = sbase + (uint32_t)slot * LN_STAGE;
        const uint32_t sB = sA + LNA_BYTES;
        #pragma unroll
        for (int r = 0; r < 2; r++) {
            const int idx = tid + 256 * r;     // 0..511 -> A 128 rows x 4 segs
            const int row = idx >> 2, seg = idx & 3;
            CP_ASYNC16(sA + (uint32_t)(row * HROW_B + seg * 16),
                       Ag + (size_t)row * K + seg * 8);
        }
        #pragma unroll
        for (int r = 0; r < 4; r++) {
            const int idx = tid + 256 * r;     // 0..1023 -> B 256 rows x 4 segs
            const int row = idx >> 2, seg = idx & 3;
            CP_ASYNC16(sB + (uint32_t)(row * HROW_B + seg * 16),
                       Bg + (size_t)row * K + seg * 8);
        }
    };

    issue_chunk(0, 0); CP_COMMIT();

    const int l15 = lane & 15;
    const int koff = (lane >> 4) * 16;
    const int nchunk = K >> 5;                  // 8

    for (int c = 0; c < nchunk; c++) {
        if (c + 1 < nchunk) {
            issue_chunk(c + 1, (c + 1) & 1); CP_COMMIT();
            asm volatile("cp.async.wait_group 1;");
        } else {
            asm volatile("cp.async.wait_group 0;");
        }
        __syncthreads();

        const uint32_t sA = sbase + (uint32_t)(c & 1) * LN_STAGE;
        const uint32_t sB = sA + LNA_BYTES;

        #pragma unroll
        for (int ks = 0; ks < 2; ks++) {
            uint32_t a[4][4];
            #pragma unroll
            for (int mi = 0; mi < 4; mi++)
                LDSM4(a[mi], sA + (uint32_t)((wm * 64 + mi * 16 + l15) * HROW_B + ks * 32 + koff));
            uint32_t bf[4][4];
            #pragma unroll
            for (int g = 0; g < 4; g++)
                LDSM4(bf[g], sB + (uint32_t)((wn * 64 + g * 16 + l15) * HROW_B + ks * 32 + koff));
            #pragma unroll
            for (int mi = 0; mi < 4; mi++)
                #pragma unroll
                for (int g = 0; g < 4; g++)
                    #pragma unroll
                    for (int h = 0; h < 2; h++)
                        mma_f16(acc[mi][g * 2 + h], a[mi], bf[g][h], bf[g][h + 2]);
        }
        __syncthreads();
    }

    // Add bias in place
    #pragma unroll
    for (int mi = 0; mi < 4; mi++)
        #pragma unroll
        for (int ni = 0; ni < 8; ni++) {
            const int col = wn * 64 + ni * 8 + tig * 2;
            acc[mi][ni][0] += bias[col];
            acc[mi][ni][1] += bias[col + 1];
            acc[mi][ni][2] += bias[col];
            acc[mi][ni][3] += bias[col + 1];
        }

    // Row sums (this thread covers 8 rows: mi x {lo,hi}, 16 cols each)
    float rsum[4][2], rsq[4][2];
    #pragma unroll
    for (int mi = 0; mi < 4; mi++) {
        float slo = 0.f, qlo = 0.f, shi = 0.f, qhi = 0.f;
        #pragma unroll
        for (int ni = 0; ni < 8; ni++) {
            slo += acc[mi][ni][0] + acc[mi][ni][1];
            qlo += acc[mi][ni][0] * acc[mi][ni][0] + acc[mi][ni][1] * acc[mi][ni][1];
            shi += acc[mi][ni][2] + acc[mi][ni][3];
            qhi += acc[mi][ni][2] * acc[mi][ni][2] + acc[mi][ni][3] * acc[mi][ni][3];
        }
        // reduce over tig (lanes gid*4 + tig)
        #pragma unroll
        for (int o = 1; o <= 2; o <<= 1) {
            slo += __shfl_xor_sync(0xffffffffu, slo, o);
            qlo += __shfl_xor_sync(0xffffffffu, qlo, o);
            shi += __shfl_xor_sync(0xffffffffu, shi, o);
            qhi += __shfl_xor_sync(0xffffffffu, qhi, o);
        }
        rsum[mi][0] = slo; rsq[mi][0] = qlo;
        rsum[mi][1] = shi; rsq[mi][1] = qhi;
    }

    // cross-wn reduce via smem: sums at smf[rr*4+wn], sq at smf[512 + rr*4+wn]
    if (tig == 0) {
        #pragma unroll
        for (int mi = 0; mi < 4; mi++) {
            const int rlo = wm * 64 + mi * 16 + gid;
            smf[rlo * 4 + wn] = rsum[mi][0];
            smf[512 + rlo * 4 + wn] = rsq[mi][0];
            smf[(rlo + 8) * 4 + wn] = rsum[mi][1];
            smf[512 + (rlo + 8) * 4 + wn] = rsq[mi][1];
        }
    }
    __syncthreads();

    #pragma unroll
    for (int mi = 0; mi < 4; mi++) {
        #pragma unroll
        for (int lh = 0; lh < 2; lh++) {
            const int rr = wm * 64 + mi * 16 + gid + lh * 8;
            float ts = smf[rr * 4 + 0] + smf[rr * 4 + 1] + smf[rr * 4 + 2] + smf[rr * 4 + 3];
            float tq = smf[512 + rr * 4 + 0] + smf[512 + rr * 4 + 1] +
                       smf[512 + rr * 4 + 2] + smf[512 + rr * 4 + 3];
            const float mu = ts * (1.f / FD_);
            const float var = tq * (1.f / FD_) - mu * mu;
            const float rstd = rsqrtf(var + 1e-5f);

            const int tok = m0 + rr;
            const int h = tok & 15;
            const int bl = tok >> 4;                 // b*L + l
            const int l = bl & (L_ - 1);
            const int b = bl >> 12;
            float mscale = 1.f;
            if (use_mask) mscale = 1.f + mask[bl];
            __half* orow = out + ((size_t)((b * NH_ + h)) * L_ + l) * FD_;

            #pragma unroll
            for (int ni = 0; ni < 8; ni++) {
                const int col = wn * 64 + ni * 8 + tig * 2;
                const float g0 = gamma[col], g1 = gamma[col + 1];
                const float be0 = beta[col], be1 = beta[col + 1];
                float y0 = ((acc[mi][ni][lh * 2 + 0] - mu) * rstd * g0 + be0) * mscale;
                float y1 = ((acc[mi][ni][lh * 2 + 1] - mu) * rstd * g1 + be1) * mscale;
                *(__half2*)(orow + col) = __floats2half2_rn(y0, y1);
            }
        }
    }
}

// ---------------------------------------------------------------------------
// kv via tensor cores with trans-ldmatrix.
// Per (bh, split): C[f=256][d=128] partial over l in [split*512, +512).
// kf head-major [bh][l][f] half; v tok-major half [b*L+l][h*128+d].
// Output fp32 partial kvp[split][bh][d][f] (transposed store).
// ---------------------------------------------------------------------------
#define KV_KFROW 528                         // bytes per kf smem row (32 l rows)
#define KV_VROW  272
#define KV_STAGE (32 * KV_KFROW + 32 * KV_VROW)   // 25600
#define KV_SMEM  (2 * KV_STAGE)              // 51200

__global__ __launch_bounds__(256, 1) void kv_tc_kernel(
    const __half* __restrict__ kf, const __half* __restrict__ vh,
    float* __restrict__ kvp)
{
    extern __shared__ char smraw[];
    const uint32_t sbase = smem_u32(smraw);
    const int tid = threadIdx.x;
    const int wid = tid >> 5, lane = tid & 31;
    const int wm = wid & 3, wn = wid >> 2;       // 4 (f) x 2 (d)
    const int gid = lane >> 2, tig = lane & 3;
    const int bh = blockIdx.x, split = blockIdx.y;
    const int b = bh >> 4, h = bh & 15;
    const int k0 = split * 512;

    const __half* kfb = kf + (size_t)bh * L_ * FD_;

    float acc[4][8][4];
    #pragma unroll
    for (int mi = 0; mi < 4; mi++)
        #pragma unroll
        for (int ni = 0; ni < 8; ni++)
            #pragma unroll
            for (int j = 0; j < 4; j++) acc[mi][ni][j] = 0.f;

    auto issue_chunk = [&](int c, int slot) {
        const int l0 = k0 + c * 32;
        const uint32_t sKF = sbase + (uint32_t)slot * KV_STAGE;
        const uint32_t sV = sKF + 32 * KV_KFROW;
        #pragma unroll
        for (int r = 0; r < 4; r++) {
            const int idx = tid + 256 * r;       // 1024: 32 rows x 32 segs
            const int row = idx >> 5, seg = idx & 31;
            CP_ASYNC16(sKF + (uint32_t)(row * KV_KFROW + seg * 16),
                       kfb + (size_t)(l0 + row) * FD_ + seg * 8);
        }
        #pragma unroll
        for (int r = 0; r < 2; r++) {
            const int idx = tid + 256 * r;       // 512: 32 rows x 16 segs
            const int row = idx >> 4, seg = idx & 15;
            CP_ASYNC16(sV + (uint32_t)(row * KV_VROW + seg * 16),
                       vh + ((size_t)(b * L_ + l0 + row)) * HS_ + h * HD_ + seg * 8);
        }
    };

    issue_chunk(0, 0); CP_COMMIT();

    const int quad = lane >> 3, qr = lane & 7;
    const int nchunk = 16;

    for (int c = 0; c < nchunk; c++) {
        if (c + 1 < nchunk) {
            issue_chunk(c + 1, (c + 1) & 1); CP_COMMIT();
            asm volatile("cp.async.wait_group 1;");
        } else {
            asm volatile("cp.async.wait_group 0;");
        }
        __syncthreads();

        const uint32_t sKF = sbase + (uint32_t)(c & 1) * KV_STAGE;
        const uint32_t sV = sKF + 32 * KV_KFROW;

        #pragma unroll
        for (int ks = 0; ks < 2; ks++) {
            const int lrow = ks * 16 + (quad >> 1) * 8 + qr;
            const int coff = (quad & 1) * 8;     // half units
            uint32_t a[4][4];
            #pragma unroll
            for (int mi = 0; mi < 4; mi++) {
                const int f0 = wm * 64 + mi * 16;
                LDSM4T(a[mi], sKF + (uint32_t)(lrow * KV_KFROW + (f0 + coff) * 2));
            }
            uint32_t bf[4][4];
            #pragma unroll
            for (int g = 0; g < 4; g++) {
                const int d0 = wn * 64 + g * 16;
                LDSM4T(bf[g], sV + (uint32_t)(lrow * KV_VROW + (d0 + coff) * 2));
            }
            #pragma unroll
            for (int mi = 0; mi < 4; mi++)
                #pragma unroll
                for (int g = 0; g < 4; g++)
                    #pragma unroll
                    for (int hh = 0; hh < 2; hh++)
                        mma_f16(acc[mi][g * 2 + hh], a[mi], bf[g][hh], bf[g][hh + 2]);
        }
        __syncthreads();
    }

    // Store transposed: kvp[(split*32+bh)][n=d][m=f]
    float* outp = kvp + ((size_t)(split * BH_ + bh)) * HD_ * FD_;
    #pragma unroll
    for (int mi = 0; mi < 4; mi++) {
        const int m = wm * 64 + mi * 16 + gid;
        #pragma unroll
        for (int ni = 0; ni < 8; ni++) {
            const int n = wn * 64 + ni * 8 + tig * 2;
            outp[(size_t)n * FD_ + m]           = acc[mi][ni][0];
            outp[(size_t)(n + 1) * FD_ + m]     = acc[mi][ni][1];
            outp[(size_t)n * FD_ + m + 8]       = acc[mi][ni][2];
            outp[(size_t)(n + 1) * FD_ + m + 8] = acc[mi][ni][3];
        }
    }
}

// Reduce 8 kv partials -> kvT half [bh][d][f]
__global__ __launch_bounds__(256) void kv_reduce_kernel(
    const float* __restrict__ kvp, __half* __restrict__ kvT)
{
    const int i = blockIdx.x * 256 + threadIdx.x;    // over 262144 float4 groups
    const size_t stride = (size_t)BH_ * HD_ * FD_;   // 1048576
    float4 s = *(const float4*)(kvp + (size_t)i * 4);
    #pragma unroll
    for (int p = 1; p < 8; p++) {
        float4 t = *(const float4*)(kvp + p * stride + (size_t)i * 4);
        s.x += t.x; s.y += t.y; s.z += t.z; s.w += t.w;
    }
    __half2 h0 = __floats2half2_rn(s.x, s.y);
    __half2 h1 = __floats2half2_rn(s.z, s.w);
    uint2 o;
    o.x = *(uint32_t*)&h0; o.y = *(uint32_t*)&h1;
    *(uint2*)(kvT + (size_t)i * 4) = o;
}

// ---------------------------------------------------------------------------
// ksum from head-major kf half
// ---------------------------------------------------------------------------
__global__ void zero_ksum_kernel(float* __restrict__ ks)
{
    ks[blockIdx.x * FD_ + threadIdx.x] = 0.f;
}

__global__ __launch_bounds__(256) void ksum_h_kernel(
    const __half* __restrict__ kf, float* __restrict__ ks)
{
    const int bh = blockIdx.x, chunk = blockIdx.y;
    const int f = threadIdx.x;
    const __half* base = kf + (size_t)bh * L_ * FD_ + (size_t)chunk * 512 * FD_ + f;
    float acc = 0.f;
    for (int l = 0; l < 512; ++l)
        acc += __half2float(base[(size_t)l * FD_]);
    atomicAdd(&ks[bh * FD_ + f], acc);
}

// ---------------------------------------------------------------------------
// denom[bh*L + l] = dot(qf[bh,l,:], ksum[bh,:]) ; warp per row
// ---------------------------------------------------------------------------
__global__ __launch_bounds__(256) void denom_kernel(
    const __half* __restrict__ qf, const float* __restrict__ ks,
    float* __restrict__ den)
{
    const int wid = threadIdx.x >> 5, lane = threadIdx.x & 31;
    const int r = blockIdx.x * 8 + wid;              // 0..131071
    const int bh = r >> 12;
    const uint4 p = *(const uint4*)(qf + (size_t)r * FD_ + lane * 8);
    const float* kp = ks + bh * FD_ + lane * 8;
    const __half2* h = (const __half2*)&p;
    float acc = 0.f;
    #pragma unroll
    for (int j = 0; j < 4; j++) {
        float2 f2 = __half22float2(h[j]);
        acc += f2.x * kp[j * 2] + f2.y * kp[j * 2 + 1];
    }
    #pragma unroll
    for (int o = 16; o; o >>= 1) acc += __shfl_down_sync(0xffffffffu, acc, o);
    if (lane == 0) den[r] = acc;
}

// ---------------------------------------------------------------------------
// attn via tensor cores: per (bh, ltile): out = (qf @ kvT^T) / denom
// M=128 (l), N=128 (d), K=256. Same mainloop as gemm_h.
// ---------------------------------------------------------------------------
__global__ __launch_bounds__(256, 2) void attn_tc_kernel(
    const __half* __restrict__ qf, const __half* __restrict__ kvT,
    const float* __restrict__ den, __half* __restrict__ out)
{
    extern __shared__ char smraw[];
    const uint32_t sbase = smem_u32(smraw);
    const int tid = threadIdx.x;
    const int wid = tid >> 5, lane = tid & 31;
    const int wm = wid & 3, wn = wid >> 2;
    const int gid = lane >> 2, tig = lane & 3;
    const int bh = blockIdx.x, l0 = blockIdx.y * 128;
    const int b = bh >> 4, h = bh & 15;
    const int K = FD_;

    const __half* A = qf + (size_t)bh * L_ * FD_ + (size_t)l0 * FD_;
    const __half* BT = kvT + (size_t)bh * HD_ * FD_;

    float acc[2][8][4];
    #pragma unroll
    for (int mi = 0; mi < 2; mi++)
        #pragma unroll
        for (int ni = 0; ni < 8; ni++)
            #pragma unroll
            for (int j = 0; j < 4; j++) acc[mi][ni][j] = 0.f;

    auto issue_chunk = [&](int c, int slot) {
        const uint32_t sA = sbase + (uint32_t)slot * STAGE_BYTES;
        const uint32_t sB = sA + A_BYTES;
        #pragma unroll
        for (int r = 0; r < 2; r++) {
            const int idx = tid + 256 * r;
            const int row = idx >> 2, seg = idx & 3;
            const uint32_t so = (uint32_t)(row * HROW_B + seg * 16);
            CP_ASYNC16(sA + so, A + (size_t)row * K + c * 32 + seg * 8);
            CP_ASYNC16(sB + so, BT + (size_t)row * K + c * 32 + seg * 8);
        }
    };

    issue_chunk(0, 0); CP_COMMIT();
    issue_chunk(1, 1); CP_COMMIT();

    const int l15 = lane & 15;
    const int koff = (lane >> 4) * 16;
    const int nchunk = K >> 5;                  // 8

    int slot = 0;
    for (int c = 0; c < nchunk; c++) {
        if (c + 2 < nchunk) issue_chunk(c + 2, (c + 2) % 3);
        CP_COMMIT();
        asm volatile("cp.async.wait_group 2;");
        __syncthreads();

        const uint32_t sA = sbase + (uint32_t)slot * STAGE_BYTES;
        const uint32_t sB = sA + A_BYTES;

        #pragma unroll
        for (int ks = 0; ks < 2; ks++) {
            uint32_t a[2][4];
            #pragma unroll
            for (int mi = 0; mi < 2; mi++)
                LDSM4(a[mi], sA + (uint32_t)((wm * 32 + mi * 16 + l15) * HROW_B + ks * 32 + koff));
            uint32_t bf[4][4];
            #pragma unroll
            for (int g = 0; g < 4; g++)
                LDSM4(bf[g], sB + (uint32_t)((wn * 64 + g * 16 + l15) * HROW_B + ks * 32 + koff));
            #pragma unroll
            for (int g = 0; g < 4; g++)
                #pragma unroll
                for (int hh = 0; hh < 2; hh++) {
                    mma_f16(acc[0][g * 2 + hh], a[0], bf[g][hh], bf[g][hh + 2]);
                    mma_f16(acc[1][g * 2 + hh], a[1], bf[g][hh], bf[g][hh + 2]);
                }
        }
        __syncthreads();
        slot++; if (slot == 3) slot = 0;
    }

    #pragma unroll
    for (int mi = 0; mi < 2; mi++) {
        const int row = wm * 32 + mi * 16 + gid;
        const int llo = l0 + row, lhi = llo + 8;
        const float ilo = 1.f / (den[bh * L_ + llo] + 1e-8f);
        const float ihi = 1.f / (den[bh * L_ + lhi] + 1e-8f);
        __half* olo = out + ((size_t)(b * L_ + llo)) * HS_ + h * HD_;
        __half* ohi = out + ((size_t)(b * L_ + lhi)) * HS_ + h * HD_;
        #pragma unroll
        for (int ni = 0; ni < 8; ni++) {
            const int col = wn * 64 + ni * 8 + tig * 2;
            *(__half2*)(olo + col) = __floats2half2_rn(acc[mi][ni][0] * ilo,
                                                        acc[mi][ni][1] * ilo);
            *(__half2*)(ohi + col) = __floats2half2_rn(acc[mi][ni][2] * ihi,
                                                        acc[mi][ni][3] * ihi);
        }
    }
}

// ---------------------------------------------------------------------------
// Transpose to half + f2h
// ---------------------------------------------------------------------------
__global__ __launch_bounds__(256) void transpose_h_kernel(
    const float* __restrict__ src, __half* __restrict__ dst, int R, int C)
{
    __shared__ float t[32][33];
    const int bx = blockIdx.x * 32;
    const int by = blockIdx.y * 32;
    const int tx = threadIdx.x, ty = threadIdx.y;
    #pragma unroll
    for (int i = 0; i < 32; i += 8)
        t[ty + i][tx] = src[(size_t)(by + ty + i) * C + bx + tx];
    __syncthreads();
    #pragma unroll
    for (int i = 0; i < 32; i += 8)
        dst[(size_t)(bx + ty + i) * R + by + tx] = __float2half_rn(t[tx][ty + i]);
}

__global__ __launch_bounds__(256) void f2h_kernel(
    const float4* __restrict__ src, uint2* __restrict__ dst, int n4)
{
    const int i = blockIdx.x * 256 + threadIdx.x;
    if (i < n4) {
        float4 v = src[i];
        __half2 a = __floats2half2_rn(v.x, v.y);
        __half2 b = __floats2half2_rn(v.z, v.w);
        uint2 o;
        o.x = *(uint32_t*)&a;
        o.y = *(uint32_t*)&b;
        dst[i] = o;
    }
}

// ---------------------------------------------------------------------------
// Host launch
// ---------------------------------------------------------------------------
extern "C" void kernel_launch(void* const* d_in, const int* in_sizes, int n_in,
                              void* d_out, int out_size)
{
    (void)in_sizes; (void)n_in; (void)out_size;
    const float* X    = (const float*)d_in[0];
    const float* mask = (const float*)d_in[1];
    const float* Wq   = (const float*)d_in[2];
    const float* bq   = (const float*)d_in[3];
    const float* Wk   = (const float*)d_in[4];
    const float* bk   = (const float*)d_in[5];
    const float* Wv   = (const float*)d_in[6];
    const float* bv   = (const float*)d_in[7];
    const float* Wo   = (const float*)d_in[8];
    const float* bo   = (const float*)d_in[9];
    const float* Wf1  = (const float*)d_in[10];
    const float* bf1  = (const float*)d_in[11];
    const float* Wf2  = (const float*)d_in[12];
    const float* bf2  = (const float*)d_in[13];
    const float* ln_g = (const float*)d_in[14];
    const float* ln_b = (const float*)d_in[15];

    float* scratch = nullptr;
    cudaGetSymbolAddress((void**)&scratch, g_scratch);
    __half* Xh    = (__half*)(scratch + OFF_XH);
    __half* qh    = (__half*)(scratch + OFF_QH);
    __half* kh    = (__half*)(scratch + OFF_KH);
    __half* vh    = (__half*)(scratch + OFF_VH);
    __half* tmph  = (__half*)(scratch + OFF_TMPH);
    __half* qfh   = (__half*)(scratch + OFF_QFH);
    __half* kfh   = (__half*)(scratch + OFF_KFH);
    float*  kvp   = scratch + OFF_KVP;
    __half* kvT   = (__half*)(scratch + OFF_KVT);
    float*  ksbuf = scratch + OFF_KSUM;
    float*  den   = scratch + OFF_DEN;
    __half* attnh = (__half*)(scratch + OFF_ATTNH);
    __half* WqT   = (__half*)(scratch + OFF_WQT);
    __half* WkT   = (__half*)(scratch + OFF_WKT);
    __half* WvT   = (__half*)(scratch + OFF_WVT);
    __half* WoT   = (__half*)(scratch + OFF_WOT);
    __half* Wf1T  = (__half*)(scratch + OFF_WF1T);
    __half* Wf2T  = (__half*)(scratch + OFF_WF2T);

    static bool attr_set = false;
    if (!attr_set) {
        cudaFuncSetAttribute(gemm_h_kernel,
                             cudaFuncAttributeMaxDynamicSharedMemorySize, GEMM_SMEM);
        cudaFuncSetAttribute(gemm_ln_kernel,
                             cudaFuncAttributeMaxDynamicSharedMemorySize, LN_SMEM);
        cudaFuncSetAttribute(kv_tc_kernel,
                             cudaFuncAttributeMaxDynamicSharedMemorySize, KV_SMEM);
        cudaFuncSetAttribute(attn_tc_kernel,
                             cudaFuncAttributeMaxDynamicSharedMemorySize, GEMM_SMEM);
        attr_set = true;
    }

    dim3 t8(32, 8);
    transpose_h_kernel<<<dim3(HS_/32, HS_/32), t8>>>(Wq, WqT, HS_, HS_);
    transpose_h_kernel<<<dim3(HS_/32, HS_/32), t8>>>(Wk, WkT, HS_, HS_);
    transpose_h_kernel<<<dim3(HS_/32, HS_/32), t8>>>(Wv, WvT, HS_, HS_);
    transpose_h_kernel<<<dim3(HS_/32, HS_/32), t8>>>(Wo, WoT, HS_, HS_);
    transpose_h_kernel<<<dim3(FD_/32, HD_/32), t8>>>(Wf1, Wf1T, HD_, FD_);
    transpose_h_kernel<<<dim3(FD_/32, FD_/32), t8>>>(Wf2, Wf2T, FD_, FD_);

    f2h_kernel<<<(NROWS * HS_ / 4 + 255) / 256, 256>>>(
        (const float4*)X, (uint2*)Xh, NROWS * HS_ / 4);

    dim3 blk(256);
    dim3 gBig(HS_ / 128, NROWS / 128);

    // QKV projections (all half out)
    gemm_h_kernel<<<gBig, blk, GEMM_SMEM>>>(Xh, WqT, bq, qh, NROWS, HS_, HS_, 0, 1);
    gemm_h_kernel<<<gBig, blk, GEMM_SMEM>>>(Xh, WkT, bk, kh, NROWS, HS_, HS_, 0, 1);
    gemm_h_kernel<<<gBig, blk, GEMM_SMEM>>>(Xh, WvT, bv, vh, NROWS, HS_, HS_, 0, 1);

    dim3 gF1(FD_ / 128, NTOK / 128);

    // feature_map(q): gemm1 + (gemm2 + LN fused) -> head-major qfh
    gemm_h_kernel<<<gF1, blk, GEMM_SMEM>>>(qh, Wf1T, bf1, tmph, NTOK, FD_, HD_, 1, 1);
    gemm_ln_kernel<<<NTOK / 128, blk, LN_SMEM>>>(tmph, Wf2T, bf2, ln_g, ln_b,
                                                 mask, qfh, 0);

    // feature_map(k) * (1+mask) -> head-major kfh
    gemm_h_kernel<<<gF1, blk, GEMM_SMEM>>>(kh, Wf1T, bf1, tmph, NTOK, FD_, HD_, 1, 1);
    gemm_ln_kernel<<<NTOK / 128, blk, LN_SMEM>>>(tmph, Wf2T, bf2, ln_g, ln_b,
                                                 mask, kfh, 1);

    // k_sum
    zero_ksum_kernel<<<BH_, FD_>>>(ksbuf);
    ksum_h_kernel<<<dim3(BH_, 8), 256>>>(kfh, ksbuf);

    // kv (tensor cores, 8-way L split) + reduce -> kvT half
    kv_tc_kernel<<<dim3(BH_, 8), blk, KV_SMEM>>>(kfh, vh, kvp);
    kv_reduce_kernel<<<1024, 256>>>(kvp, kvT);

    // denom
    denom_kernel<<<NTOK / 8, 256>>>(qfh, ksbuf, den);

    // attn (tensor cores) -> tok-major half
    attn_tc_kernel<<<dim3(BH_, L_ / 128), blk, GEMM_SMEM>>>(qfh, kvT, den, attnh);

    // output projection (fp32 out)
    gemm_h_kernel<<<gBig, blk, GEMM_SMEM>>>(attnh, WoT, bo, (float*)d_out,
                                            NROWS, HS_, HS_, 0, 0);
}